// round 7
// baseline (speedup 1.0000x reference)
#include <cuda_runtime.h>

#define EPSV 1e-5f
#define B_   16
#define T_   2048
#define S_   2112        // padded stride for global conv buffers

// Global buffers:
//  g_r1 : [b][c1][u]  conv1 post-ReLU, abs pos a' = u-5,  u in [0,2106]
//  g_r2p: [b][u][32]  conv2 PRE-act,   abs pos a  = u-2,  u in [0,2100]
//  g_r3p: [b][u][16]  conv3 PRE-act,   abs pos a  = u,    u in [0,2096]
__device__ __align__(128) float g_r1 [B_*64*S_];
__device__ __align__(128) float g_r2p[B_*S_*32];
__device__ __align__(128) float g_r3p[B_*S_*16];
__device__ __align__(128) float g_feats[B_*T_*16];
__device__ __align__(128) float g_pre [B_*T_*256];   // layer0 input projection
__device__ __align__(128) float g_h[B_*T_*64];       // h2 (fc input)

// ======================= Phase A: global conv stack =======================
// XP[i] = x[i-49] for 49<=i<=2096 else 0.

__global__ void __launch_bounds__(256) conv1g_kernel(
    const float* __restrict__ x,
    const float* __restrict__ c1w, const float* __restrict__ c1b,
    const float* __restrict__ g1, const float* __restrict__ b1p,
    const float* __restrict__ m1, const float* __restrict__ v1)
{
    __shared__ float xw[264];
    __shared__ float w1s[576];
    __shared__ float s1[64], e1[64];
    const int tid = threadIdx.x;
    const int b = blockIdx.y;
    const int u0 = blockIdx.x * 256;
    for (int j = tid; j < 264; j += 256) {
        int i = u0 - 9 + j;                      // XP index
        xw[j] = (i >= 49 && i <= 2096) ? x[b*2048 + i - 49] : 0.f;
    }
    for (int i = tid; i < 576; i += 256) w1s[i] = c1w[i];
    if (tid < 64) {
        float s = g1[tid] * rsqrtf(v1[tid] + EPSV);
        s1[tid] = s; e1[tid] = (c1b[tid] - m1[tid]) * s + b1p[tid];
    }
    __syncthreads();
    int u = u0 + tid;
    if (u < 2107) {
        float xv[9];
        #pragma unroll
        for (int k = 0; k < 9; ++k) xv[k] = xw[tid + k];
        for (int c = 0; c < 64; ++c) {
            float acc = 0.f;
            #pragma unroll
            for (int k = 0; k < 9; ++k) acc += w1s[c*9 + k] * xv[k];
            float r = acc * s1[c] + e1[c];
            g_r1[(b*64 + c)*S_ + u] = r > 0.f ? r : 0.f;
        }
    }
}

#define C2G_SMEM_FLOATS (14336 + 64*72 + 64)
__global__ void __launch_bounds__(256) conv2g_kernel(
    const float* __restrict__ c2w, const float* __restrict__ c2b,
    const float* __restrict__ g2, const float* __restrict__ b2p,
    const float* __restrict__ m2, const float* __restrict__ v2)
{
    extern __shared__ float sm[];
    float* w2s = sm;               // [(c1*7+k)*32 + c2]
    float* r1t = sm + 14336;       // [64][72]
    float* s2  = r1t + 4608;
    float* e2  = s2 + 32;
    const int tid = threadIdx.x;
    const int b = blockIdx.y;
    const int u0 = blockIdx.x * 64;

    for (int i = tid; i < 14336; i += 256) {
        int c2 = i / 448; int r = i % 448; int c1 = r / 7; int k = r % 7;
        w2s[(c1*7 + k)*32 + c2] = c2w[i];
    }
    if (tid < 32) {
        float s = g2[tid] * rsqrtf(v2[tid] + EPSV);
        s2[tid] = s; e2[tid] = (c2b[tid] - m2[tid]) * s + b2p[tid];
    }
    for (int f = tid; f < 64*70; f += 256) {
        int c1 = f / 70, i = f - c1*70;
        int u = u0 + i;
        r1t[c1*72 + i] = (u <= 2106) ? g_r1[(b*64 + c1)*S_ + u] : 0.f;
    }
    __syncthreads();

    const int c2 = tid & 31, slot = tid >> 5;   // 8 slots x 8 positions
    float acc[8];
    #pragma unroll
    for (int j = 0; j < 8; ++j) acc[j] = 0.f;
    for (int c1 = 0; c1 < 64; ++c1) {
        const float* rp = r1t + c1*72 + slot*8;
        float v[14];
        #pragma unroll
        for (int i = 0; i < 14; ++i) v[i] = rp[i];
        const float* wp = w2s + c1*224 + c2;
        #pragma unroll
        for (int k = 0; k < 7; ++k) {
            float wv = wp[k*32];
            #pragma unroll
            for (int j = 0; j < 8; ++j) acc[j] += wv * v[k + j];
        }
    }
    float ss = s2[c2], bb = e2[c2];
    #pragma unroll
    for (int j = 0; j < 8; ++j) {
        int u = u0 + slot*8 + j;
        if (u <= 2100)
            g_r2p[((size_t)b*S_ + u)*32 + c2] = acc[j] * ss + bb;   // PRE-act, chan-last
    }
}

__global__ void __launch_bounds__(256) conv3g_kernel(
    const float* __restrict__ c3w, const float* __restrict__ c3b,
    const float* __restrict__ g3, const float* __restrict__ b3p,
    const float* __restrict__ m3, const float* __restrict__ v3)
{
    __shared__ float w3s[2560];      // [(c2*5+k)*16 + c3]
    __shared__ float r2t[32*72];
    __shared__ float s3[16], e3[16];
    const int tid = threadIdx.x;
    const int b = blockIdx.y;
    const int u0 = blockIdx.x * 64;

    for (int i = tid; i < 2560; i += 256) {
        int c3 = i / 160; int r = i % 160; int cc = r / 5; int k = r % 5;
        w3s[(cc*5 + k)*16 + c3] = c3w[i];
    }
    if (tid < 16) {
        float s = g3[tid] * rsqrtf(v3[tid] + EPSV);
        s3[tid] = s; e3[tid] = (c3b[tid] - m3[tid]) * s + b3p[tid];
    }
    // coalesced: cc fastest
    for (int f = tid; f < 32*68; f += 256) {
        int cc = f & 31, i = f >> 5;
        int u = u0 + i;
        float g = (u <= 2100) ? g_r2p[((size_t)b*S_ + u)*32 + cc] : 0.f;
        r2t[cc*72 + i] = g > 0.f ? g : 0.f;      // ReLU on load
    }
    __syncthreads();

    const int c3 = tid & 15, slot = tid >> 4;   // 16 slots x 4 positions
    float acc[4] = {0.f, 0.f, 0.f, 0.f};
    for (int cc = 0; cc < 32; ++cc) {
        const float* rp = r2t + cc*72 + slot*4;
        float v[8];
        #pragma unroll
        for (int i = 0; i < 8; ++i) v[i] = rp[i];
        const float* wp = w3s + cc*80 + c3;
        #pragma unroll
        for (int k = 0; k < 5; ++k) {
            float wv = wp[k*16];
            #pragma unroll
            for (int j = 0; j < 4; ++j) acc[j] += wv * v[k + j];
        }
    }
    float ss = s3[c3], bb = e3[c3];
    #pragma unroll
    for (int j = 0; j < 4; ++j) {
        int u = u0 + slot*4 + j;
        if (u <= 2096)
            g_r3p[((size_t)b*S_ + u)*16 + c3] = acc[j] * ss + bb;   // PRE-act, chan-last
    }
}

// ======================= Phase B: persistent fused boundary kernel =======================
#define BND_SMEM_FLOATS (14336 + 2560 + 576 + 176 + 64 + 4096 + 3072 + 256)
#define NCTA  1024
#define NGRP  8

__global__ void __launch_bounds__(256, 2) bnd_fused_kernel(
    const float* __restrict__ x,
    const float* __restrict__ c1w, const float* __restrict__ c1b,
    const float* __restrict__ g1, const float* __restrict__ b1p,
    const float* __restrict__ m1, const float* __restrict__ v1,
    const float* __restrict__ c2w,
    const float* __restrict__ g2, const float* __restrict__ v2,
    const float* __restrict__ c3w,
    const float* __restrict__ g3, const float* __restrict__ v3)
{
    extern __shared__ float sm[];
    float* w2s    = sm;               // 14336
    float* w3s    = sm + 14336;       // 2560
    float* w1s    = sm + 16896;       // 576
    float* s1s    = sm + 17472;       // 64
    float* e1s    = sm + 17536;       // 64
    float* s2s    = sm + 17600;       // 32
    float* s3s    = sm + 17632;       // 16 (+pad to 17648)
    float* xs     = sm + 17648;       // 64
    float* dstage = sm + 17712;       // 4096
    float* stage3 = sm + 21808;       // 3072
    float* fbuf   = sm + 24880;       // 256

    const int tid = threadIdx.x;

    // ---- one-time staging ----
    for (int i = tid; i < 14336; i += 256) {
        int c2 = i / 448; int r = i % 448; int c1 = r / 7; int k = r % 7;
        w2s[(c1*7 + k)*32 + c2] = c2w[i];
    }
    for (int i = tid; i < 2560; i += 256) {
        int c3 = i / 160; int r = i % 160; int cc = r / 5; int k = r % 5;
        w3s[(cc*5 + k)*16 + c3] = c3w[i];
    }
    for (int i = tid; i < 576; i += 256) w1s[i] = c1w[i];
    if (tid < 64) {
        float s = g1[tid] * rsqrtf(v1[tid] + EPSV);
        s1s[tid] = s; e1s[tid] = (c1b[tid] - m1[tid]) * s + b1p[tid];
    } else if (tid < 96) {
        int c = tid - 64;
        s2s[c] = g2[c] * rsqrtf(v2[c] + EPSV);
    } else if (tid < 112) {
        int c = tid - 96;
        s3s[c] = g3[c] * rsqrtf(v3[c] + EPSV);
    }
    __syncthreads();

    for (int it = 0; it < NGRP; ++it) {
        const int gid = blockIdx.x * NGRP + it;
        const int b  = gid >> 9;                 // 512 groups per batch
        const int t0 = (gid & 511) * 4;

        // ---- 1) stage x values ----
        if (tid < 64) {
            int w = tid >> 4, r = tid & 15;
            int side = r >> 3, j = r & 7;
            int i = t0 + w + (side ? 42 + j : j);
            float v = (i >= 49 && i <= 2096) ? x[b*2048 + i - 49] : 0.f;
            xs[side*32 + w*8 + j] = v;
        }
        __syncthreads();

        // ---- 2) stage delta1 ----
        for (int s = tid; s < 4096; s += 256) {
            int qi = s & 7, c1 = (s >> 3) & 63, side = (s >> 9) & 1, w = s >> 10;
            int t = t0 + w;
            float val = 0.f;
            if (qi < 7) {
                if (side == 0) {
                    float gl = g_r1[(b*64 + c1)*S_ + t + qi + 2];
                    if (qi < 3) val = -gl;
                    else {
                        int q = qi - 3;
                        float pre = 0.f;
                        #pragma unroll
                        for (int k = 0; k < 9; ++k)
                            if (k >= 4 - q) pre += w1s[c1*9 + k] * xs[w*8 + q - 4 + k];
                        float rv = pre * s1s[c1] + e1s[c1];
                        val = (rv > 0.f ? rv : 0.f) - gl;
                    }
                } else {
                    float gl = g_r1[(b*64 + c1)*S_ + t + 51 + qi];
                    if (qi >= 4) val = -gl;
                    else {
                        int q = 46 + qi;
                        float pre = 0.f;
                        #pragma unroll
                        for (int k = 0; k < 9; ++k)
                            if (k <= 53 - q) pre += w1s[c1*9 + k] * xs[32 + w*8 + qi + k];
                        float rv = pre * s1s[c1] + e1s[c1];
                        val = (rv > 0.f ? rv : 0.f) - gl;
                    }
                }
            }
            dstage[s] = val;
        }
        __syncthreads();

        // ---- 3) conv2 correction -> stage3 ----
        {
            const int c2 = tid & 31, side = (tid >> 5) & 1, w = tid >> 6;
            const int t = t0 + w;
            float acc[7];
            #pragma unroll
            for (int p = 0; p < 7; ++p) acc[p] = 0.f;

            for (int c1 = 0; c1 < 64; ++c1) {
                const float* dp = dstage + ((w*2 + side)*64 + c1)*8;
                float4 A = *(const float4*)dp;
                float4 Bv = *(const float4*)(dp + 4);
                float d[8] = {A.x, A.y, A.z, A.w, Bv.x, Bv.y, Bv.z, Bv.w};
                const float* wp = w2s + c1*224 + c2;
                float wk[7];
                #pragma unroll
                for (int k = 0; k < 7; ++k) wk[k] = wp[k*32];
                if (side == 0) {
                    #pragma unroll
                    for (int p = 0; p < 7; ++p)
                        #pragma unroll
                        for (int k = 0; k < 7; ++k)
                            if (k + p <= 6) acc[p] += wk[k] * d[p + k];
                } else {
                    #pragma unroll
                    for (int p = 0; p < 7; ++p)
                        #pragma unroll
                        for (int k = 0; k < 7; ++k)
                            if (k >= 6 - p) acc[p] += wk[k] * d[p + k - 6];
                }
            }

            const float s2v = s2s[c2];
            float* sp = stage3 + ((w*2 + side)*32 + c2)*12;
            const float* gpb = g_r2p + ((size_t)b*S_ + t)*32 + c2;
            if (side == 0) {
                #pragma unroll
                for (int p = 0; p < 7; ++p) {
                    float gpre = gpb[(p + 2)*32];
                    float pre = gpre + s2v * acc[p];
                    sp[2 + p] = (pre > 0.f ? pre : 0.f) - (gpre > 0.f ? gpre : 0.f);
                }
                float e0 = gpb[0], e1v = gpb[32];
                sp[0] = -(e0 > 0.f ? e0 : 0.f);
                sp[1] = -(e1v > 0.f ? e1v : 0.f);
            } else {
                #pragma unroll
                for (int p = 0; p < 7; ++p) {
                    float gpre = gpb[(45 + p)*32];
                    float pre = gpre + s2v * acc[p];
                    sp[p] = (pre > 0.f ? pre : 0.f) - (gpre > 0.f ? gpre : 0.f);
                }
                float e0 = gpb[52*32], e1v = gpb[53*32];
                sp[7] = -(e0 > 0.f ? e0 : 0.f);
                sp[8] = -(e1v > 0.f ? e1v : 0.f);
            }
            sp[9] = 0.f; sp[10] = 0.f; sp[11] = 0.f;
        }
        __syncthreads();

        // ---- 4) conv3 correction + interior sums ----
        if (tid < 128) {
            const int c3 = tid & 15, ws = tid >> 4;
            const int side = ws & 1, w = ws >> 1;
            const int t = t0 + w;
            float acc[9];
            #pragma unroll
            for (int p = 0; p < 9; ++p) acc[p] = 0.f;

            for (int c2 = 0; c2 < 32; ++c2) {
                const float* dp = stage3 + (ws*32 + c2)*12;
                float4 A = *(const float4*)dp;
                float4 Bv = *(const float4*)(dp + 4);
                float C = dp[8];
                float d[9] = {A.x, A.y, A.z, A.w, Bv.x, Bv.y, Bv.z, Bv.w, C};
                const float* wp = w3s + c2*80 + c3;
                float wk[5];
                #pragma unroll
                for (int k = 0; k < 5; ++k) wk[k] = wp[k*16];
                if (side == 0) {
                    #pragma unroll
                    for (int p = 0; p < 9; ++p)
                        #pragma unroll
                        for (int k = 0; k < 5; ++k)
                            if (p + k <= 8) acc[p] += wk[k] * d[p + k];
                } else {
                    #pragma unroll
                    for (int p = 0; p < 9; ++p)
                        #pragma unroll
                        for (int k = 0; k < 5; ++k)
                            if (k >= 4 - p) acc[p] += wk[k] * d[p + k - 4];
                }
            }

            float sum = 0.f;
            const float s3v = s3s[c3];
            const float* rp = g_r3p + ((size_t)b*S_ + t)*16 + c3;
            #pragma unroll
            for (int j = 0; j < 9; ++j) {
                int P = side ? 41 + j : j;
                float pre = rp[P*16] + s3v * acc[j];
                sum += pre > 0.f ? pre : 0.f;
            }
            fbuf[ws*16 + c3] = sum;
        } else {
            const int tt = tid - 128;
            const int c3 = tt & 15, ws = tt >> 4;
            const int side = ws & 1, w = ws >> 1;
            const int t = t0 + w;
            const float* rp = g_r3p + ((size_t)b*S_ + t + 9 + side*16)*16 + c3;
            float sum = 0.f;
            #pragma unroll
            for (int i = 0; i < 16; ++i) {
                float g = rp[i*16];
                sum += g > 0.f ? g : 0.f;
            }
            fbuf[128 + ws*16 + c3] = sum;
        }
        __syncthreads();

        // ---- 5) combine -> feats ----
        if (tid < 64) {
            int w = tid >> 4, c3 = tid & 15;
            float sum = fbuf[(w*2    )*16 + c3] + fbuf[(w*2 + 1)*16 + c3]
                      + fbuf[128 + (w*2)*16 + c3] + fbuf[128 + (w*2 + 1)*16 + c3];
            g_feats[(b*T_ + t0 + w)*16 + c3] = sum * 0.02f;
        }
        __syncthreads();
    }
}

// ---------------- pre-GEMM (layer0 input projection) ----------------
__global__ void __launch_bounds__(256) gemm_pre16(
    const float* __restrict__ wih, const float* __restrict__ bi, const float* __restrict__ bh)
{
    __shared__ float ws[16*256];
    __shared__ float ft[16*16];
    __shared__ float bs[256];
    int tid = threadIdx.x;
    for (int i = tid; i < 4096; i += 256) { int j = i >> 4, k = i & 15; ws[k*256 + j] = wih[i]; }
    bs[tid] = bi[tid] + bh[tid];
    int r0 = blockIdx.x * 16;
    ft[tid] = g_feats[r0*16 + tid];
    __syncthreads();
    float acc[16];
    #pragma unroll
    for (int r = 0; r < 16; ++r) acc[r] = bs[tid];
    #pragma unroll
    for (int k = 0; k < 16; ++k) {
        float w = ws[k*256 + tid];
        #pragma unroll
        for (int r = 0; r < 16; ++r) acc[r] += w * ft[r*16 + k];
    }
    #pragma unroll
    for (int r = 0; r < 16; ++r) g_pre[(r0 + r)*256 + tid] = acc[r];
}

// ---------------- single-CTA fused two-layer LSTM ----------------
__device__ __forceinline__ float sigf(float x)  { return __fdividef(1.f, 1.f + __expf(-x)); }
__device__ __forceinline__ float tanhq(float x) { return __fdividef(2.f, 1.f + __expf(-2.f*x)) - 1.f; }

__device__ __forceinline__ unsigned long long pk2(float a, float b) {
    unsigned long long r;
    asm("mov.b64 %0, {%1, %2};" : "=l"(r) : "f"(a), "f"(b));
    return r;
}
__device__ __forceinline__ void fma2(unsigned long long& d,
                                     unsigned long long a, unsigned long long b) {
    asm("fma.rn.f32x2 %0, %1, %2, %0;" : "+l"(d) : "l"(a), "l"(b));
}
__device__ __forceinline__ float2 upk2(unsigned long long v) {
    float2 f;
    asm("mov.b64 {%0, %1}, %2;" : "=f"(f.x), "=f"(f.y) : "l"(v));
    return f;
}

// smem: w1p2 [16*256 ulonglong2] = 64KB, then h1s[64], h2s[64], a0s[256], a1s[256]
#define LSTM_SMEM_BYTES (65536 + (64 + 64 + 256 + 256) * 4)

// grid 16 (one CTA per batch elem), 512 threads:
//  tid<256  : layer0, gate g, whh0 row in regs
//  tid>=256 : layer1, gate g, whh1 row in regs, wih1 from smem
__global__ void __launch_bounds__(512, 1) lstm_fused(
    const float* __restrict__ whh0, const float* __restrict__ wih1,
    const float* __restrict__ whh1,
    const float* __restrict__ bih1, const float* __restrict__ bhh1)
{
    extern __shared__ char smraw[];
    ulonglong2* w1p2 = (ulonglong2*)smraw;                 // [k4*256 + g]
    float* h1s = (float*)(smraw + 65536);                  // 64
    float* h2s = h1s + 64;                                 // 64
    float* a0s = h2s + 64;                                 // 256
    float* a1s = a0s + 256;                                // 256

    const int tid = threadIdx.x;
    const int b = blockIdx.x;
    const bool isP = tid < 256;
    const int g = tid & 255;

    // stage wih1 into smem as packed f32x2 quads, [k4][g] for conflict-free reads
    for (int idx = tid; idx < 16*256; idx += 512) {
        int k4 = idx >> 8, gg = idx & 255;
        const float4 wv = *(const float4*)(wih1 + gg*64 + k4*4);
        ulonglong2 e;
        e.x = pk2(wv.x, wv.y);
        e.y = pk2(wv.z, wv.w);
        w1p2[k4*256 + gg] = e;
    }
    // own recurrent weights (whh0 row for P, whh1 row for C)
    unsigned long long wr[32];
    {
        const float4* r = (const float4*)((isP ? whh0 : whh1) + g*64);
        #pragma unroll
        for (int q = 0; q < 16; ++q) {
            float4 a = r[q]; wr[2*q] = pk2(a.x, a.y); wr[2*q+1] = pk2(a.z, a.w);
        }
    }
    const float bias1v = isP ? 0.f : (bih1[g] + bhh1[g]);
    const float* preB = g_pre + (size_t)b * T_ * 256;
    float* hB = g_h + (size_t)b * T_ * 64;

    if (tid < 64) { h1s[tid] = 0.f; h2s[tid] = 0.f; }
    float cst = 0.f;                     // c0 (tid<64) / c1 (tid 256..319)
    float pg = 0.f, pcn = 0.f, cg = 0.f;
    if (isP) { pg = preB[g]; pcn = preB[256 + g]; }
    __syncthreads();

    for (int k = 0; k <= T_; ++k) {
        // ---- phase 1: per-gate activations (parallel across 256 threads/layer) ----
        if (isP) {
            if (k < T_) {
                float v = pg;
                a0s[g] = ((g >> 6) == 2) ? tanhq(v) : sigf(v);
            }
        } else if (k >= 1) {
            float v = cg;
            a1s[g] = ((g >> 6) == 2) ? tanhq(v) : sigf(v);
        }
        __syncthreads();
        // ---- phase 2: state updates (short serial chain) ----
        if (tid < 64) {
            if (k < T_) {
                float c_ = a0s[64 + tid]*cst + a0s[tid]*a0s[128 + tid];
                cst = c_;
                h1s[tid] = a0s[192 + tid]*tanhq(c_);
            }
        } else if (tid >= 256 && tid < 320 && k >= 1) {
            int u = tid - 256;
            float c_ = a1s[64 + u]*cst + a1s[u]*a1s[128 + u];
            cst = c_;
            float h = a1s[192 + u]*tanhq(c_);
            h2s[u] = h;
            hB[(k - 1)*64 + u] = h;
        }
        __syncthreads();
        // ---- phase 3: dots ----
        if (k < T_) {
            const ulonglong2* h1q = (const ulonglong2*)h1s;
            if (isP) {
                unsigned long long b0 = 0ull, b1 = 0ull;
                #pragma unroll
                for (int q = 0; q < 16; ++q) {
                    ulonglong2 hv = h1q[q];
                    fma2(b0, wr[2*q],   hv.x);
                    fma2(b1, wr[2*q+1], hv.y);
                }
                float2 f0 = upk2(b0), f1 = upk2(b1);
                pg = pcn + (f0.x + f0.y) + (f1.x + f1.y);   // gates0(k+1)
                int tn = (k + 2 < T_) ? k + 2 : T_ - 1;
                pcn = preB[tn*256 + g];
            } else {
                unsigned long long b0 = 0ull, b1 = 0ull, b2 = 0ull, b3 = 0ull;
                const ulonglong2* h2q = (const ulonglong2*)h2s;
                const ulonglong2* wq = w1p2 + g;
                #pragma unroll
                for (int q = 0; q < 16; ++q) {
                    ulonglong2 hv = h1q[q];
                    ulonglong2 wv = wq[q*256];
                    fma2(b0, wv.x, hv.x);               // wih1 . h1(k)
                    fma2(b1, wv.y, hv.y);
                    ulonglong2 h2v = h2q[q];
                    fma2(b2, wr[2*q],   h2v.x);         // whh1 . h2(k-1)
                    fma2(b3, wr[2*q+1], h2v.y);
                }
                float2 f0 = upk2(b0), f1 = upk2(b1), f2 = upk2(b2), f3 = upk2(b3);
                cg = bias1v + ((f0.x + f0.y) + (f1.x + f1.y))
                            + ((f2.x + f2.y) + (f3.x + f3.y));   // gates1(k)
            }
        }
    }
}

// ---------------- FC head ----------------
__global__ void __launch_bounds__(256) fc_kernel(
    const float* __restrict__ w1, const float* __restrict__ b1,
    const float* __restrict__ w2, const float* __restrict__ b2,
    float* __restrict__ out)
{
    __shared__ __align__(16) float w1s[2048];
    __shared__ float w2s[64];
    __shared__ float b1s[32];
    int tid = threadIdx.x;
    for (int i = tid; i < 2048; i += 256) w1s[i] = w1[i];
    if (tid < 64) w2s[tid] = w2[tid];
    if (tid < 32) b1s[tid] = b1[tid];
    __syncthreads();

    int gid = blockIdx.x*256 + tid;
    const float4* h4p = (const float4*)(g_h + (size_t)gid * 64);
    float4 h[16];
    #pragma unroll
    for (int q = 0; q < 16; ++q) h[q] = h4p[q];

    float l0 = b2[0], l1 = b2[1];
    #pragma unroll
    for (int i = 0; i < 32; ++i) {
        float acc = b1s[i];
        const float4* wr = (const float4*)(w1s + i*64);
        #pragma unroll
        for (int q = 0; q < 16; ++q) {
            float4 w4 = wr[q];
            acc += w4.x*h[q].x + w4.y*h[q].y + w4.z*h[q].z + w4.w*h[q].w;
        }
        acc = acc > 0.f ? acc : 0.f;
        l0 += w2s[i] * acc;
        l1 += w2s[32 + i] * acc;
    }
    ((float2*)out)[gid] = make_float2(l0, l1);
}

// ---------------- launch ----------------
extern "C" void kernel_launch(void* const* d_in, const int* in_sizes, int n_in,
                              void* d_out, int out_size)
{
    const float* x     = (const float*)d_in[0];
    const float* c1w   = (const float*)d_in[1];
    const float* c1b   = (const float*)d_in[2];
    const float* bn1g  = (const float*)d_in[3];
    const float* bn1b  = (const float*)d_in[4];
    const float* bn1m  = (const float*)d_in[5];
    const float* bn1v  = (const float*)d_in[6];
    const float* c2w   = (const float*)d_in[7];
    const float* c2b   = (const float*)d_in[8];
    const float* bn2g  = (const float*)d_in[9];
    const float* bn2b  = (const float*)d_in[10];
    const float* bn2m  = (const float*)d_in[11];
    const float* bn2v  = (const float*)d_in[12];
    const float* c3w   = (const float*)d_in[13];
    const float* c3b   = (const float*)d_in[14];
    const float* bn3g  = (const float*)d_in[15];
    const float* bn3b  = (const float*)d_in[16];
    const float* bn3m  = (const float*)d_in[17];
    const float* bn3v  = (const float*)d_in[18];
    const float* wih0  = (const float*)d_in[19];
    const float* whh0  = (const float*)d_in[20];
    const float* bih0  = (const float*)d_in[21];
    const float* bhh0  = (const float*)d_in[22];
    const float* wih1  = (const float*)d_in[23];
    const float* whh1  = (const float*)d_in[24];
    const float* bih1  = (const float*)d_in[25];
    const float* bhh1  = (const float*)d_in[26];
    const float* fc1w  = (const float*)d_in[27];
    const float* fc1b  = (const float*)d_in[28];
    const float* fc2w  = (const float*)d_in[29];
    const float* fc2b  = (const float*)d_in[30];

    cudaFuncSetAttribute(conv2g_kernel, cudaFuncAttributeMaxDynamicSharedMemorySize,
                         C2G_SMEM_FLOATS * 4);
    cudaFuncSetAttribute(bnd_fused_kernel, cudaFuncAttributeMaxDynamicSharedMemorySize,
                         BND_SMEM_FLOATS * 4);
    cudaFuncSetAttribute(lstm_fused, cudaFuncAttributeMaxDynamicSharedMemorySize,
                         LSTM_SMEM_BYTES);

    // Phase A: global conv stack
    conv1g_kernel<<<dim3(9, B_), 256>>>(x, c1w, c1b, bn1g, bn1b, bn1m, bn1v);
    conv2g_kernel<<<dim3(33, B_), 256, C2G_SMEM_FLOATS * 4>>>(c2w, c2b, bn2g, bn2b, bn2m, bn2v);
    conv3g_kernel<<<dim3(33, B_), 256>>>(c3w, c3b, bn3g, bn3b, bn3m, bn3v);

    // Phase B: persistent fused boundary corrections -> feats
    bnd_fused_kernel<<<NCTA, 256, BND_SMEM_FLOATS * 4>>>(
        x, c1w, c1b, bn1g, bn1b, bn1m, bn1v,
        c2w, bn2g, bn2v, c3w, bn3g, bn3v);

    // layer0 input projection
    gemm_pre16<<<(B_ * T_) / 16, 256>>>(wih0, bih0, bhh0);

    // both LSTM layers, fused in one CTA per batch element
    lstm_fused<<<B_, 512, LSTM_SMEM_BYTES>>>(whh0, wih1, whh1, bih1, bhh1);

    // FC head
    fc_kernel<<<(B_ * T_) / 256, 256>>>(fc1w, fc1b, fc2w, fc2b, (float*)d_out);
}

// round 8
// speedup vs baseline: 1.7039x; 1.7039x over previous
#include <cuda_runtime.h>

#define EPSV 1e-5f
#define B_   16
#define T_   2048
#define S_   2112        // padded stride for global conv buffers

// Global buffers:
//  g_r1 : [b][c1][u]  conv1 post-ReLU, abs pos a' = u-5,  u in [0,2106]
//  g_r2p: [b][u][32]  conv2 PRE-act,   abs pos a  = u-2,  u in [0,2100]
//  g_r3p: [b][u][16]  conv3 PRE-act,   abs pos a  = u,    u in [0,2096]
__device__ __align__(128) float g_r1 [B_*64*S_];
__device__ __align__(128) float g_r2p[B_*S_*32];
__device__ __align__(128) float g_r3p[B_*S_*16];
__device__ __align__(128) float g_feats[B_*T_*16];
__device__ __align__(128) float g_pre [B_*T_*256];   // layer0 input projection
__device__ __align__(128) float g_pre1[B_*T_*256];   // layer1 input projection (pipeline)
__device__ __align__(128) float g_h[B_*T_*64];       // h2 (fc input)
__device__ int g_flag[B_];

// ======================= Phase A: global conv stack =======================
// XP[i] = x[i-49] for 49<=i<=2096 else 0.

__global__ void __launch_bounds__(256) conv1g_kernel(
    const float* __restrict__ x,
    const float* __restrict__ c1w, const float* __restrict__ c1b,
    const float* __restrict__ g1, const float* __restrict__ b1p,
    const float* __restrict__ m1, const float* __restrict__ v1)
{
    __shared__ float xw[264];
    __shared__ float w1s[576];
    __shared__ float s1[64], e1[64];
    const int tid = threadIdx.x;
    const int b = blockIdx.y;
    const int u0 = blockIdx.x * 256;
    for (int j = tid; j < 264; j += 256) {
        int i = u0 - 9 + j;                      // XP index
        xw[j] = (i >= 49 && i <= 2096) ? x[b*2048 + i - 49] : 0.f;
    }
    for (int i = tid; i < 576; i += 256) w1s[i] = c1w[i];
    if (tid < 64) {
        float s = g1[tid] * rsqrtf(v1[tid] + EPSV);
        s1[tid] = s; e1[tid] = (c1b[tid] - m1[tid]) * s + b1p[tid];
    }
    __syncthreads();
    int u = u0 + tid;
    if (u < 2107) {
        float xv[9];
        #pragma unroll
        for (int k = 0; k < 9; ++k) xv[k] = xw[tid + k];
        for (int c = 0; c < 64; ++c) {
            float acc = 0.f;
            #pragma unroll
            for (int k = 0; k < 9; ++k) acc += w1s[c*9 + k] * xv[k];
            float r = acc * s1[c] + e1[c];
            g_r1[(b*64 + c)*S_ + u] = r > 0.f ? r : 0.f;
        }
    }
}

#define C2G_SMEM_FLOATS (14336 + 64*72 + 64)
__global__ void __launch_bounds__(256) conv2g_kernel(
    const float* __restrict__ c2w, const float* __restrict__ c2b,
    const float* __restrict__ g2, const float* __restrict__ b2p,
    const float* __restrict__ m2, const float* __restrict__ v2)
{
    extern __shared__ float sm[];
    float* w2s = sm;               // [(c1*7+k)*32 + c2]
    float* r1t = sm + 14336;       // [64][72]
    float* s2  = r1t + 4608;
    float* e2  = s2 + 32;
    const int tid = threadIdx.x;
    const int b = blockIdx.y;
    const int u0 = blockIdx.x * 64;

    for (int i = tid; i < 14336; i += 256) {
        int c2 = i / 448; int r = i % 448; int c1 = r / 7; int k = r % 7;
        w2s[(c1*7 + k)*32 + c2] = c2w[i];
    }
    if (tid < 32) {
        float s = g2[tid] * rsqrtf(v2[tid] + EPSV);
        s2[tid] = s; e2[tid] = (c2b[tid] - m2[tid]) * s + b2p[tid];
    }
    for (int f = tid; f < 64*70; f += 256) {
        int c1 = f / 70, i = f - c1*70;
        int u = u0 + i;
        r1t[c1*72 + i] = (u <= 2106) ? g_r1[(b*64 + c1)*S_ + u] : 0.f;
    }
    __syncthreads();

    const int c2 = tid & 31, slot = tid >> 5;   // 8 slots x 8 positions
    float acc[8];
    #pragma unroll
    for (int j = 0; j < 8; ++j) acc[j] = 0.f;
    for (int c1 = 0; c1 < 64; ++c1) {
        const float* rp = r1t + c1*72 + slot*8;
        float v[14];
        #pragma unroll
        for (int i = 0; i < 14; ++i) v[i] = rp[i];
        const float* wp = w2s + c1*224 + c2;
        #pragma unroll
        for (int k = 0; k < 7; ++k) {
            float wv = wp[k*32];
            #pragma unroll
            for (int j = 0; j < 8; ++j) acc[j] += wv * v[k + j];
        }
    }
    float ss = s2[c2], bb = e2[c2];
    #pragma unroll
    for (int j = 0; j < 8; ++j) {
        int u = u0 + slot*8 + j;
        if (u <= 2100)
            g_r2p[((size_t)b*S_ + u)*32 + c2] = acc[j] * ss + bb;   // PRE-act, chan-last
    }
}

__global__ void __launch_bounds__(256) conv3g_kernel(
    const float* __restrict__ c3w, const float* __restrict__ c3b,
    const float* __restrict__ g3, const float* __restrict__ b3p,
    const float* __restrict__ m3, const float* __restrict__ v3)
{
    __shared__ float w3s[2560];      // [(c2*5+k)*16 + c3]
    __shared__ float r2t[32*72];
    __shared__ float s3[16], e3[16];
    const int tid = threadIdx.x;
    const int b = blockIdx.y;
    const int u0 = blockIdx.x * 64;

    for (int i = tid; i < 2560; i += 256) {
        int c3 = i / 160; int r = i % 160; int cc = r / 5; int k = r % 5;
        w3s[(cc*5 + k)*16 + c3] = c3w[i];
    }
    if (tid < 16) {
        float s = g3[tid] * rsqrtf(v3[tid] + EPSV);
        s3[tid] = s; e3[tid] = (c3b[tid] - m3[tid]) * s + b3p[tid];
    }
    // coalesced: cc fastest
    for (int f = tid; f < 32*68; f += 256) {
        int cc = f & 31, i = f >> 5;
        int u = u0 + i;
        float g = (u <= 2100) ? g_r2p[((size_t)b*S_ + u)*32 + cc] : 0.f;
        r2t[cc*72 + i] = g > 0.f ? g : 0.f;      // ReLU on load
    }
    __syncthreads();

    const int c3 = tid & 15, slot = tid >> 4;   // 16 slots x 4 positions
    float acc[4] = {0.f, 0.f, 0.f, 0.f};
    for (int cc = 0; cc < 32; ++cc) {
        const float* rp = r2t + cc*72 + slot*4;
        float v[8];
        #pragma unroll
        for (int i = 0; i < 8; ++i) v[i] = rp[i];
        const float* wp = w3s + cc*80 + c3;
        #pragma unroll
        for (int k = 0; k < 5; ++k) {
            float wv = wp[k*16];
            #pragma unroll
            for (int j = 0; j < 4; ++j) acc[j] += wv * v[k + j];
        }
    }
    float ss = s3[c3], bb = e3[c3];
    #pragma unroll
    for (int j = 0; j < 4; ++j) {
        int u = u0 + slot*4 + j;
        if (u <= 2096)
            g_r3p[((size_t)b*S_ + u)*16 + c3] = acc[j] * ss + bb;   // PRE-act, chan-last
    }
}

// ======================= Phase B: persistent fused boundary kernel =======================
#define BND_SMEM_FLOATS (14336 + 2560 + 576 + 176 + 64 + 4096 + 3072 + 256)
#define NCTA  1024
#define NGRP  8

__global__ void __launch_bounds__(256, 2) bnd_fused_kernel(
    const float* __restrict__ x,
    const float* __restrict__ c1w, const float* __restrict__ c1b,
    const float* __restrict__ g1, const float* __restrict__ b1p,
    const float* __restrict__ m1, const float* __restrict__ v1,
    const float* __restrict__ c2w,
    const float* __restrict__ g2, const float* __restrict__ v2,
    const float* __restrict__ c3w,
    const float* __restrict__ g3, const float* __restrict__ v3)
{
    extern __shared__ float sm[];
    float* w2s    = sm;               // 14336
    float* w3s    = sm + 14336;       // 2560
    float* w1s    = sm + 16896;       // 576
    float* s1s    = sm + 17472;       // 64
    float* e1s    = sm + 17536;       // 64
    float* s2s    = sm + 17600;       // 32
    float* s3s    = sm + 17632;       // 16 (+pad to 17648)
    float* xs     = sm + 17648;       // 64
    float* dstage = sm + 17712;       // 4096
    float* stage3 = sm + 21808;       // 3072
    float* fbuf   = sm + 24880;       // 256

    const int tid = threadIdx.x;

    // ---- one-time staging ----
    for (int i = tid; i < 14336; i += 256) {
        int c2 = i / 448; int r = i % 448; int c1 = r / 7; int k = r % 7;
        w2s[(c1*7 + k)*32 + c2] = c2w[i];
    }
    for (int i = tid; i < 2560; i += 256) {
        int c3 = i / 160; int r = i % 160; int cc = r / 5; int k = r % 5;
        w3s[(cc*5 + k)*16 + c3] = c3w[i];
    }
    for (int i = tid; i < 576; i += 256) w1s[i] = c1w[i];
    if (tid < 64) {
        float s = g1[tid] * rsqrtf(v1[tid] + EPSV);
        s1s[tid] = s; e1s[tid] = (c1b[tid] - m1[tid]) * s + b1p[tid];
    } else if (tid < 96) {
        int c = tid - 64;
        s2s[c] = g2[c] * rsqrtf(v2[c] + EPSV);
    } else if (tid < 112) {
        int c = tid - 96;
        s3s[c] = g3[c] * rsqrtf(v3[c] + EPSV);
    }
    __syncthreads();

    for (int it = 0; it < NGRP; ++it) {
        const int gid = blockIdx.x * NGRP + it;
        const int b  = gid >> 9;                 // 512 groups per batch
        const int t0 = (gid & 511) * 4;

        // ---- 1) stage x values ----
        if (tid < 64) {
            int w = tid >> 4, r = tid & 15;
            int side = r >> 3, j = r & 7;
            int i = t0 + w + (side ? 42 + j : j);
            float v = (i >= 49 && i <= 2096) ? x[b*2048 + i - 49] : 0.f;
            xs[side*32 + w*8 + j] = v;
        }
        __syncthreads();

        // ---- 2) stage delta1 ----
        for (int s = tid; s < 4096; s += 256) {
            int qi = s & 7, c1 = (s >> 3) & 63, side = (s >> 9) & 1, w = s >> 10;
            int t = t0 + w;
            float val = 0.f;
            if (qi < 7) {
                if (side == 0) {
                    float gl = g_r1[(b*64 + c1)*S_ + t + qi + 2];
                    if (qi < 3) val = -gl;
                    else {
                        int q = qi - 3;
                        float pre = 0.f;
                        #pragma unroll
                        for (int k = 0; k < 9; ++k)
                            if (k >= 4 - q) pre += w1s[c1*9 + k] * xs[w*8 + q - 4 + k];
                        float rv = pre * s1s[c1] + e1s[c1];
                        val = (rv > 0.f ? rv : 0.f) - gl;
                    }
                } else {
                    float gl = g_r1[(b*64 + c1)*S_ + t + 51 + qi];
                    if (qi >= 4) val = -gl;
                    else {
                        int q = 46 + qi;
                        float pre = 0.f;
                        #pragma unroll
                        for (int k = 0; k < 9; ++k)
                            if (k <= 53 - q) pre += w1s[c1*9 + k] * xs[32 + w*8 + qi + k];
                        float rv = pre * s1s[c1] + e1s[c1];
                        val = (rv > 0.f ? rv : 0.f) - gl;
                    }
                }
            }
            dstage[s] = val;
        }
        __syncthreads();

        // ---- 3) conv2 correction -> stage3 ----
        {
            const int c2 = tid & 31, side = (tid >> 5) & 1, w = tid >> 6;
            const int t = t0 + w;
            float acc[7];
            #pragma unroll
            for (int p = 0; p < 7; ++p) acc[p] = 0.f;

            for (int c1 = 0; c1 < 64; ++c1) {
                const float* dp = dstage + ((w*2 + side)*64 + c1)*8;
                float4 A = *(const float4*)dp;
                float4 Bv = *(const float4*)(dp + 4);
                float d[8] = {A.x, A.y, A.z, A.w, Bv.x, Bv.y, Bv.z, Bv.w};
                const float* wp = w2s + c1*224 + c2;
                float wk[7];
                #pragma unroll
                for (int k = 0; k < 7; ++k) wk[k] = wp[k*32];
                if (side == 0) {
                    #pragma unroll
                    for (int p = 0; p < 7; ++p)
                        #pragma unroll
                        for (int k = 0; k < 7; ++k)
                            if (k + p <= 6) acc[p] += wk[k] * d[p + k];
                } else {
                    #pragma unroll
                    for (int p = 0; p < 7; ++p)
                        #pragma unroll
                        for (int k = 0; k < 7; ++k)
                            if (k >= 6 - p) acc[p] += wk[k] * d[p + k - 6];
                }
            }

            const float s2v = s2s[c2];
            float* sp = stage3 + ((w*2 + side)*32 + c2)*12;
            const float* gpb = g_r2p + ((size_t)b*S_ + t)*32 + c2;
            if (side == 0) {
                #pragma unroll
                for (int p = 0; p < 7; ++p) {
                    float gpre = gpb[(p + 2)*32];
                    float pre = gpre + s2v * acc[p];
                    sp[2 + p] = (pre > 0.f ? pre : 0.f) - (gpre > 0.f ? gpre : 0.f);
                }
                float e0 = gpb[0], e1v = gpb[32];
                sp[0] = -(e0 > 0.f ? e0 : 0.f);
                sp[1] = -(e1v > 0.f ? e1v : 0.f);
            } else {
                #pragma unroll
                for (int p = 0; p < 7; ++p) {
                    float gpre = gpb[(45 + p)*32];
                    float pre = gpre + s2v * acc[p];
                    sp[p] = (pre > 0.f ? pre : 0.f) - (gpre > 0.f ? gpre : 0.f);
                }
                float e0 = gpb[52*32], e1v = gpb[53*32];
                sp[7] = -(e0 > 0.f ? e0 : 0.f);
                sp[8] = -(e1v > 0.f ? e1v : 0.f);
            }
            sp[9] = 0.f; sp[10] = 0.f; sp[11] = 0.f;
        }
        __syncthreads();

        // ---- 4) conv3 correction + interior sums ----
        if (tid < 128) {
            const int c3 = tid & 15, ws = tid >> 4;
            const int side = ws & 1, w = ws >> 1;
            const int t = t0 + w;
            float acc[9];
            #pragma unroll
            for (int p = 0; p < 9; ++p) acc[p] = 0.f;

            for (int c2 = 0; c2 < 32; ++c2) {
                const float* dp = stage3 + (ws*32 + c2)*12;
                float4 A = *(const float4*)dp;
                float4 Bv = *(const float4*)(dp + 4);
                float C = dp[8];
                float d[9] = {A.x, A.y, A.z, A.w, Bv.x, Bv.y, Bv.z, Bv.w, C};
                const float* wp = w3s + c2*80 + c3;
                float wk[5];
                #pragma unroll
                for (int k = 0; k < 5; ++k) wk[k] = wp[k*16];
                if (side == 0) {
                    #pragma unroll
                    for (int p = 0; p < 9; ++p)
                        #pragma unroll
                        for (int k = 0; k < 5; ++k)
                            if (p + k <= 8) acc[p] += wk[k] * d[p + k];
                } else {
                    #pragma unroll
                    for (int p = 0; p < 9; ++p)
                        #pragma unroll
                        for (int k = 0; k < 5; ++k)
                            if (k >= 4 - p) acc[p] += wk[k] * d[p + k - 4];
                }
            }

            float sum = 0.f;
            const float s3v = s3s[c3];
            const float* rp = g_r3p + ((size_t)b*S_ + t)*16 + c3;
            #pragma unroll
            for (int j = 0; j < 9; ++j) {
                int P = side ? 41 + j : j;
                float pre = rp[P*16] + s3v * acc[j];
                sum += pre > 0.f ? pre : 0.f;
            }
            fbuf[ws*16 + c3] = sum;
        } else {
            const int tt = tid - 128;
            const int c3 = tt & 15, ws = tt >> 4;
            const int side = ws & 1, w = ws >> 1;
            const int t = t0 + w;
            const float* rp = g_r3p + ((size_t)b*S_ + t + 9 + side*16)*16 + c3;
            float sum = 0.f;
            #pragma unroll
            for (int i = 0; i < 16; ++i) {
                float g = rp[i*16];
                sum += g > 0.f ? g : 0.f;
            }
            fbuf[128 + ws*16 + c3] = sum;
        }
        __syncthreads();

        // ---- 5) combine -> feats ----
        if (tid < 64) {
            int w = tid >> 4, c3 = tid & 15;
            float sum = fbuf[(w*2    )*16 + c3] + fbuf[(w*2 + 1)*16 + c3]
                      + fbuf[128 + (w*2)*16 + c3] + fbuf[128 + (w*2 + 1)*16 + c3];
            g_feats[(b*T_ + t0 + w)*16 + c3] = sum * 0.02f;
        }
        __syncthreads();
    }
}

// ---------------- pre-GEMM (layer0 input projection) + flag reset ----------------
__global__ void __launch_bounds__(256) gemm_pre16(
    const float* __restrict__ wih, const float* __restrict__ bi, const float* __restrict__ bh)
{
    __shared__ float ws[16*256];
    __shared__ float ft[16*16];
    __shared__ float bs[256];
    int tid = threadIdx.x;
    if (blockIdx.x == 0 && tid < B_) g_flag[tid] = 0;   // reset pipeline flags each replay
    for (int i = tid; i < 4096; i += 256) { int j = i >> 4, k = i & 15; ws[k*256 + j] = wih[i]; }
    bs[tid] = bi[tid] + bh[tid];
    int r0 = blockIdx.x * 16;
    ft[tid] = g_feats[r0*16 + tid];
    __syncthreads();
    float acc[16];
    #pragma unroll
    for (int r = 0; r < 16; ++r) acc[r] = bs[tid];
    #pragma unroll
    for (int k = 0; k < 16; ++k) {
        float w = ws[k*256 + tid];
        #pragma unroll
        for (int r = 0; r < 16; ++r) acc[r] += w * ft[r*16 + k];
    }
    #pragma unroll
    for (int r = 0; r < 16; ++r) g_pre[(r0 + r)*256 + tid] = acc[r];
}

// ---------------- cross-CTA pipelined LSTM (parallel activations, batched flags) ----------------
__device__ __forceinline__ float sigf(float x)  { return __fdividef(1.f, 1.f + __expf(-x)); }
__device__ __forceinline__ float tanhq(float x) { return __fdividef(2.f, 1.f + __expf(-2.f*x)) - 1.f; }

__device__ __forceinline__ unsigned long long pk2(float a, float b) {
    unsigned long long r;
    asm("mov.b64 %0, {%1, %2};" : "=l"(r) : "f"(a), "f"(b));
    return r;
}
__device__ __forceinline__ void fma2(unsigned long long& d,
                                     unsigned long long a, unsigned long long b) {
    asm("fma.rn.f32x2 %0, %1, %2, %0;" : "+l"(d) : "l"(a), "l"(b));
}
__device__ __forceinline__ float2 upk2(unsigned long long v) {
    float2 f;
    asm("mov.b64 {%0, %1}, %2;" : "=f"(f.x), "=f"(f.y) : "l"(v));
    return f;
}
__device__ __forceinline__ void relstore(int* p, int v) {
    asm volatile("st.release.gpu.global.s32 [%0], %1;" :: "l"(p), "r"(v) : "memory");
}
__device__ __forceinline__ int acqload(const int* p) {
    int v;
    asm volatile("ld.acquire.gpu.global.s32 %0, [%1];" : "=r"(v) : "l"(p) : "memory");
    return v;
}
__device__ __forceinline__ float gact(int g, float v) {
    return ((g >> 6) == 2) ? tanhq(v) : sigf(v);   // gate order: i, f, g(tanh), o
}

// grid 32: blocks 0..15 = layer0 producers, 16..31 = layer1 consumers (one per batch elem)
__global__ void __launch_bounds__(256, 1) lstm_fused(
    const float* __restrict__ whh0, const float* __restrict__ wih1,
    const float* __restrict__ whh1,
    const float* __restrict__ bih1, const float* __restrict__ bhh1)
{
    __shared__ __align__(16) float hsm[64];
    __shared__ float acts[256];
    const int tid = threadIdx.x;

    if (blockIdx.x < 16) {
        // ============ producer: layer0 recurrence + layer1 input projection ============
        const int b = blockIdx.x;
        unsigned long long w0[32], w1[32];
        {
            const float4* r0 = (const float4*)(whh0 + tid*64);
            const float4* r1 = (const float4*)(wih1 + tid*64);
            #pragma unroll
            for (int q = 0; q < 16; ++q) {
                float4 a = r0[q]; w0[2*q] = pk2(a.x, a.y); w0[2*q+1] = pk2(a.z, a.w);
                float4 cc = r1[q]; w1[2*q] = pk2(cc.x, cc.y); w1[2*q+1] = pk2(cc.z, cc.w);
            }
        }
        const float bias1v = bih1[tid] + bhh1[tid];
        const float* preB = g_pre  + (size_t)b * T_ * 256;
        float*      pre1B = g_pre1 + (size_t)b * T_ * 256;
        float cst = 0.f;
        if (tid < 64) hsm[tid] = 0.f;
        float pg  = preB[tid];                   // gates0(0) pre-act (h1(-1)=0)
        float pcn = preB[256 + tid];             // pre0(1)
        acts[tid] = gact(tid, pg);               // activations of gates0(0)
        __syncthreads();

        for (int t = 0; t < T_; ++t) {
            // phase 2: state update (short serial chain) + batched flag publish
            if (tid < 64) {
                float c_ = acts[64 + tid]*cst + acts[tid]*acts[128 + tid];
                cst = c_;
                hsm[tid] = acts[192 + tid]*tanhq(c_);
            } else if (tid == 64 && (t & 3) == 0 && t) {
                relstore(&g_flag[b], t);         // pre1(0..t-1) published
            }
            __syncthreads();
            // phase 3: dual dot with h1(t), act in parallel, stream pre1(t)
            unsigned long long a0 = 0ull, a1 = 0ull, a2 = 0ull, a3 = 0ull;
            const ulonglong2* hp = (const ulonglong2*)hsm;
            #pragma unroll
            for (int q = 0; q < 16; ++q) {
                ulonglong2 hv = hp[q];
                fma2(a0, w0[2*q],   hv.x);
                fma2(a1, w0[2*q+1], hv.y);
                fma2(a2, w1[2*q],   hv.x);
                fma2(a3, w1[2*q+1], hv.y);
            }
            float2 f0 = upk2(a0), f1 = upk2(a1), f2 = upk2(a2), f3 = upk2(a3);
            float d0 = (f0.x + f0.y) + (f1.x + f1.y);
            float d1 = (f2.x + f2.y) + (f3.x + f3.y);
            pre1B[t*256 + tid] = d1 + bias1v;    // pre1(t)
            pg = pcn + d0;                       // gates0(t+1) pre-act
            acts[tid] = gact(tid, pg);
            int tn = (t + 2 < T_) ? t + 2 : T_ - 1;
            pcn = preB[tn*256 + tid];
            __syncthreads();
        }
        if (tid == 0) relstore(&g_flag[b], T_);  // all pre1 published
    } else {
        // ============ consumer: layer1 recurrence ============
        const int b = blockIdx.x - 16;
        unsigned long long w2r[32];
        {
            const float4* r2 = (const float4*)(whh1 + tid*64);
            #pragma unroll
            for (int q = 0; q < 16; ++q) {
                float4 a = r2[q]; w2r[2*q] = pk2(a.x, a.y); w2r[2*q+1] = pk2(a.z, a.w);
            }
        }
        const float* pre1B = g_pre1 + (size_t)b * T_ * 256;
        float* hB = g_h + (size_t)b * T_ * 64;
        float cst = 0.f;
        int flagv = 0;
        if (tid < 64) hsm[tid] = 0.f;
        while (flagv < 2) { flagv = acqload(&g_flag[b]); if (flagv < 2) __nanosleep(128); }
        float cg  = pre1B[tid];                  // gates1(0) pre-act (h2(-1)=0)
        float p1n = pre1B[256 + tid];            // pre1(1)
        acts[tid] = gact(tid, cg);
        __syncthreads();

        for (int t = 0; t < T_; ++t) {
            // phase 2: state update + h2 store
            if (tid < 64) {
                float c_ = acts[64 + tid]*cst + acts[tid]*acts[128 + tid];
                cst = c_;
                float h = acts[192 + tid]*tanhq(c_);
                hsm[tid] = h;
                hB[t*64 + tid] = h;
            }
            __syncthreads();
            // phase 3: whh1 dot with h2(t), act in parallel, batched poll + prefetch
            unsigned long long a0 = 0ull, a1 = 0ull;
            const ulonglong2* hp = (const ulonglong2*)hsm;
            #pragma unroll
            for (int q = 0; q < 16; ++q) {
                ulonglong2 hv = hp[q];
                fma2(a0, w2r[2*q],   hv.x);
                fma2(a1, w2r[2*q+1], hv.y);
            }
            float2 f0 = upk2(a0), f1 = upk2(a1);
            float d = (f0.x + f0.y) + (f1.x + f1.y);
            cg = p1n + d;                        // gates1(t+1) pre-act
            acts[tid] = gact(tid, cg);
            int tn = (t + 2 < T_) ? t + 2 : T_ - 1;
            if (flagv < tn + 1) {
                do { flagv = acqload(&g_flag[b]); if (flagv < tn + 1) __nanosleep(64); }
                while (flagv < tn + 1);
            }
            p1n = pre1B[tn*256 + tid];
            __syncthreads();
        }
    }
}

// ---------------- FC head ----------------
__global__ void __launch_bounds__(256) fc_kernel(
    const float* __restrict__ w1, const float* __restrict__ b1,
    const float* __restrict__ w2, const float* __restrict__ b2,
    float* __restrict__ out)
{
    __shared__ __align__(16) float w1s[2048];
    __shared__ float w2s[64];
    __shared__ float b1s[32];
    int tid = threadIdx.x;
    for (int i = tid; i < 2048; i += 256) w1s[i] = w1[i];
    if (tid < 64) w2s[tid] = w2[tid];
    if (tid < 32) b1s[tid] = b1[tid];
    __syncthreads();

    int gid = blockIdx.x*256 + tid;
    const float4* h4p = (const float4*)(g_h + (size_t)gid * 64);
    float4 h[16];
    #pragma unroll
    for (int q = 0; q < 16; ++q) h[q] = h4p[q];

    float l0 = b2[0], l1 = b2[1];
    #pragma unroll
    for (int i = 0; i < 32; ++i) {
        float acc = b1s[i];
        const float4* wr = (const float4*)(w1s + i*64);
        #pragma unroll
        for (int q = 0; q < 16; ++q) {
            float4 w4 = wr[q];
            acc += w4.x*h[q].x + w4.y*h[q].y + w4.z*h[q].z + w4.w*h[q].w;
        }
        acc = acc > 0.f ? acc : 0.f;
        l0 += w2s[i] * acc;
        l1 += w2s[32 + i] * acc;
    }
    ((float2*)out)[gid] = make_float2(l0, l1);
}

// ---------------- launch ----------------
extern "C" void kernel_launch(void* const* d_in, const int* in_sizes, int n_in,
                              void* d_out, int out_size)
{
    const float* x     = (const float*)d_in[0];
    const float* c1w   = (const float*)d_in[1];
    const float* c1b   = (const float*)d_in[2];
    const float* bn1g  = (const float*)d_in[3];
    const float* bn1b  = (const float*)d_in[4];
    const float* bn1m  = (const float*)d_in[5];
    const float* bn1v  = (const float*)d_in[6];
    const float* c2w   = (const float*)d_in[7];
    const float* c2b   = (const float*)d_in[8];
    const float* bn2g  = (const float*)d_in[9];
    const float* bn2b  = (const float*)d_in[10];
    const float* bn2m  = (const float*)d_in[11];
    const float* bn2v  = (const float*)d_in[12];
    const float* c3w   = (const float*)d_in[13];
    const float* c3b   = (const float*)d_in[14];
    const float* bn3g  = (const float*)d_in[15];
    const float* bn3b  = (const float*)d_in[16];
    const float* bn3m  = (const float*)d_in[17];
    const float* bn3v  = (const float*)d_in[18];
    const float* wih0  = (const float*)d_in[19];
    const float* whh0  = (const float*)d_in[20];
    const float* bih0  = (const float*)d_in[21];
    const float* bhh0  = (const float*)d_in[22];
    const float* wih1  = (const float*)d_in[23];
    const float* whh1  = (const float*)d_in[24];
    const float* bih1  = (const float*)d_in[25];
    const float* bhh1  = (const float*)d_in[26];
    const float* fc1w  = (const float*)d_in[27];
    const float* fc1b  = (const float*)d_in[28];
    const float* fc2w  = (const float*)d_in[29];
    const float* fc2b  = (const float*)d_in[30];

    cudaFuncSetAttribute(conv2g_kernel, cudaFuncAttributeMaxDynamicSharedMemorySize,
                         C2G_SMEM_FLOATS * 4);
    cudaFuncSetAttribute(bnd_fused_kernel, cudaFuncAttributeMaxDynamicSharedMemorySize,
                         BND_SMEM_FLOATS * 4);

    // Phase A: global conv stack
    conv1g_kernel<<<dim3(9, B_), 256>>>(x, c1w, c1b, bn1g, bn1b, bn1m, bn1v);
    conv2g_kernel<<<dim3(33, B_), 256, C2G_SMEM_FLOATS * 4>>>(c2w, c2b, bn2g, bn2b, bn2m, bn2v);
    conv3g_kernel<<<dim3(33, B_), 256>>>(c3w, c3b, bn3g, bn3b, bn3m, bn3v);

    // Phase B: persistent fused boundary corrections -> feats
    bnd_fused_kernel<<<NCTA, 256, BND_SMEM_FLOATS * 4>>>(
        x, c1w, c1b, bn1g, bn1b, bn1m, bn1v,
        c2w, bn2g, bn2v, c3w, bn3g, bn3v);

    // layer0 input projection (+ flag reset)
    gemm_pre16<<<(B_ * T_) / 16, 256>>>(wih0, bih0, bhh0);

    // both LSTM layers, pipelined across CTAs
    lstm_fused<<<32, 256>>>(whh0, wih1, whh1, bih1, bhh1);

    // FC head
    fc_kernel<<<(B_ * T_) / 256, 256>>>(fc1w, fc1b, fc2w, fc2b, (float*)d_out);
}

// round 9
// speedup vs baseline: 1.7355x; 1.0186x over previous
#include <cuda_runtime.h>

#define EPSV 1e-5f
#define B_   16
#define T_   2048
#define S_   2112        // padded stride for global conv buffers

// Global buffers:
__device__ __align__(128) float g_r1 [B_*64*S_];
__device__ __align__(128) float g_r2p[B_*S_*32];
__device__ __align__(128) float g_r3p[B_*S_*16];
__device__ __align__(128) float g_feats[B_*T_*16];
__device__ __align__(128) float g_pre [B_*T_*256];   // layer0 input projection
__device__ __align__(128) float g_h1  [B_*T_*64];    // h1 stream (producer -> mid)
__device__ __align__(128) float g_pre1[B_*T_*256];   // layer1 input projection (mid -> consumer)
__device__ __align__(128) float g_h[B_*T_*64];       // h2 (fc input)
__device__ int g_flag0[B_];
__device__ int g_flag1[B_];

// ======================= Phase A: global conv stack =======================
// XP[i] = x[i-49] for 49<=i<=2096 else 0.

__global__ void __launch_bounds__(256) conv1g_kernel(
    const float* __restrict__ x,
    const float* __restrict__ c1w, const float* __restrict__ c1b,
    const float* __restrict__ g1, const float* __restrict__ b1p,
    const float* __restrict__ m1, const float* __restrict__ v1)
{
    __shared__ float xw[264];
    __shared__ float w1s[576];
    __shared__ float s1[64], e1[64];
    const int tid = threadIdx.x;
    const int b = blockIdx.y;
    const int u0 = blockIdx.x * 256;
    for (int j = tid; j < 264; j += 256) {
        int i = u0 - 9 + j;                      // XP index
        xw[j] = (i >= 49 && i <= 2096) ? x[b*2048 + i - 49] : 0.f;
    }
    for (int i = tid; i < 576; i += 256) w1s[i] = c1w[i];
    if (tid < 64) {
        float s = g1[tid] * rsqrtf(v1[tid] + EPSV);
        s1[tid] = s; e1[tid] = (c1b[tid] - m1[tid]) * s + b1p[tid];
    }
    __syncthreads();
    int u = u0 + tid;
    if (u < 2107) {
        float xv[9];
        #pragma unroll
        for (int k = 0; k < 9; ++k) xv[k] = xw[tid + k];
        for (int c = 0; c < 64; ++c) {
            float acc = 0.f;
            #pragma unroll
            for (int k = 0; k < 9; ++k) acc += w1s[c*9 + k] * xv[k];
            float r = acc * s1[c] + e1[c];
            g_r1[(b*64 + c)*S_ + u] = r > 0.f ? r : 0.f;
        }
    }
}

#define C2G_SMEM_FLOATS (14336 + 64*72 + 64)
__global__ void __launch_bounds__(256) conv2g_kernel(
    const float* __restrict__ c2w, const float* __restrict__ c2b,
    const float* __restrict__ g2, const float* __restrict__ b2p,
    const float* __restrict__ m2, const float* __restrict__ v2)
{
    extern __shared__ float sm[];
    float* w2s = sm;               // [(c1*7+k)*32 + c2]
    float* r1t = sm + 14336;       // [64][72]
    float* s2  = r1t + 4608;
    float* e2  = s2 + 32;
    const int tid = threadIdx.x;
    const int b = blockIdx.y;
    const int u0 = blockIdx.x * 64;

    for (int i = tid; i < 14336; i += 256) {
        int c2 = i / 448; int r = i % 448; int c1 = r / 7; int k = r % 7;
        w2s[(c1*7 + k)*32 + c2] = c2w[i];
    }
    if (tid < 32) {
        float s = g2[tid] * rsqrtf(v2[tid] + EPSV);
        s2[tid] = s; e2[tid] = (c2b[tid] - m2[tid]) * s + b2p[tid];
    }
    for (int f = tid; f < 64*70; f += 256) {
        int c1 = f / 70, i = f - c1*70;
        int u = u0 + i;
        r1t[c1*72 + i] = (u <= 2106) ? g_r1[(b*64 + c1)*S_ + u] : 0.f;
    }
    __syncthreads();

    const int c2 = tid & 31, slot = tid >> 5;   // 8 slots x 8 positions
    float acc[8];
    #pragma unroll
    for (int j = 0; j < 8; ++j) acc[j] = 0.f;
    for (int c1 = 0; c1 < 64; ++c1) {
        const float* rp = r1t + c1*72 + slot*8;
        float v[14];
        #pragma unroll
        for (int i = 0; i < 14; ++i) v[i] = rp[i];
        const float* wp = w2s + c1*224 + c2;
        #pragma unroll
        for (int k = 0; k < 7; ++k) {
            float wv = wp[k*32];
            #pragma unroll
            for (int j = 0; j < 8; ++j) acc[j] += wv * v[k + j];
        }
    }
    float ss = s2[c2], bb = e2[c2];
    #pragma unroll
    for (int j = 0; j < 8; ++j) {
        int u = u0 + slot*8 + j;
        if (u <= 2100)
            g_r2p[((size_t)b*S_ + u)*32 + c2] = acc[j] * ss + bb;   // PRE-act, chan-last
    }
}

__global__ void __launch_bounds__(256) conv3g_kernel(
    const float* __restrict__ c3w, const float* __restrict__ c3b,
    const float* __restrict__ g3, const float* __restrict__ b3p,
    const float* __restrict__ m3, const float* __restrict__ v3)
{
    __shared__ float w3s[2560];      // [(c2*5+k)*16 + c3]
    __shared__ float r2t[32*72];
    __shared__ float s3[16], e3[16];
    const int tid = threadIdx.x;
    const int b = blockIdx.y;
    const int u0 = blockIdx.x * 64;

    for (int i = tid; i < 2560; i += 256) {
        int c3 = i / 160; int r = i % 160; int cc = r / 5; int k = r % 5;
        w3s[(cc*5 + k)*16 + c3] = c3w[i];
    }
    if (tid < 16) {
        float s = g3[tid] * rsqrtf(v3[tid] + EPSV);
        s3[tid] = s; e3[tid] = (c3b[tid] - m3[tid]) * s + b3p[tid];
    }
    // coalesced: cc fastest
    for (int f = tid; f < 32*68; f += 256) {
        int cc = f & 31, i = f >> 5;
        int u = u0 + i;
        float g = (u <= 2100) ? g_r2p[((size_t)b*S_ + u)*32 + cc] : 0.f;
        r2t[cc*72 + i] = g > 0.f ? g : 0.f;      // ReLU on load
    }
    __syncthreads();

    const int c3 = tid & 15, slot = tid >> 4;   // 16 slots x 4 positions
    float acc[4] = {0.f, 0.f, 0.f, 0.f};
    for (int cc = 0; cc < 32; ++cc) {
        const float* rp = r2t + cc*72 + slot*4;
        float v[8];
        #pragma unroll
        for (int i = 0; i < 8; ++i) v[i] = rp[i];
        const float* wp = w3s + cc*80 + c3;
        #pragma unroll
        for (int k = 0; k < 5; ++k) {
            float wv = wp[k*16];
            #pragma unroll
            for (int j = 0; j < 4; ++j) acc[j] += wv * v[k + j];
        }
    }
    float ss = s3[c3], bb = e3[c3];
    #pragma unroll
    for (int j = 0; j < 4; ++j) {
        int u = u0 + slot*4 + j;
        if (u <= 2096)
            g_r3p[((size_t)b*S_ + u)*16 + c3] = acc[j] * ss + bb;   // PRE-act, chan-last
    }
}

// ======================= Phase B: persistent fused boundary kernel =======================
#define BND_SMEM_FLOATS (14336 + 2560 + 576 + 176 + 64 + 4096 + 3072 + 256)
#define NCTA  1024
#define NGRP  8

__global__ void __launch_bounds__(256, 2) bnd_fused_kernel(
    const float* __restrict__ x,
    const float* __restrict__ c1w, const float* __restrict__ c1b,
    const float* __restrict__ g1, const float* __restrict__ b1p,
    const float* __restrict__ m1, const float* __restrict__ v1,
    const float* __restrict__ c2w,
    const float* __restrict__ g2, const float* __restrict__ v2,
    const float* __restrict__ c3w,
    const float* __restrict__ g3, const float* __restrict__ v3)
{
    extern __shared__ float sm[];
    float* w2s    = sm;               // 14336
    float* w3s    = sm + 14336;       // 2560
    float* w1s    = sm + 16896;       // 576
    float* s1s    = sm + 17472;       // 64
    float* e1s    = sm + 17536;       // 64
    float* s2s    = sm + 17600;       // 32
    float* s3s    = sm + 17632;       // 16 (+pad to 17648)
    float* xs     = sm + 17648;       // 64
    float* dstage = sm + 17712;       // 4096
    float* stage3 = sm + 21808;       // 3072
    float* fbuf   = sm + 24880;       // 256

    const int tid = threadIdx.x;

    // ---- one-time staging ----
    for (int i = tid; i < 14336; i += 256) {
        int c2 = i / 448; int r = i % 448; int c1 = r / 7; int k = r % 7;
        w2s[(c1*7 + k)*32 + c2] = c2w[i];
    }
    for (int i = tid; i < 2560; i += 256) {
        int c3 = i / 160; int r = i % 160; int cc = r / 5; int k = r % 5;
        w3s[(cc*5 + k)*16 + c3] = c3w[i];
    }
    for (int i = tid; i < 576; i += 256) w1s[i] = c1w[i];
    if (tid < 64) {
        float s = g1[tid] * rsqrtf(v1[tid] + EPSV);
        s1s[tid] = s; e1s[tid] = (c1b[tid] - m1[tid]) * s + b1p[tid];
    } else if (tid < 96) {
        int c = tid - 64;
        s2s[c] = g2[c] * rsqrtf(v2[c] + EPSV);
    } else if (tid < 112) {
        int c = tid - 96;
        s3s[c] = g3[c] * rsqrtf(v3[c] + EPSV);
    }
    __syncthreads();

    for (int it = 0; it < NGRP; ++it) {
        const int gid = blockIdx.x * NGRP + it;
        const int b  = gid >> 9;                 // 512 groups per batch
        const int t0 = (gid & 511) * 4;

        // ---- 1) stage x values ----
        if (tid < 64) {
            int w = tid >> 4, r = tid & 15;
            int side = r >> 3, j = r & 7;
            int i = t0 + w + (side ? 42 + j : j);
            float v = (i >= 49 && i <= 2096) ? x[b*2048 + i - 49] : 0.f;
            xs[side*32 + w*8 + j] = v;
        }
        __syncthreads();

        // ---- 2) stage delta1 ----
        for (int s = tid; s < 4096; s += 256) {
            int qi = s & 7, c1 = (s >> 3) & 63, side = (s >> 9) & 1, w = s >> 10;
            int t = t0 + w;
            float val = 0.f;
            if (qi < 7) {
                if (side == 0) {
                    float gl = g_r1[(b*64 + c1)*S_ + t + qi + 2];
                    if (qi < 3) val = -gl;
                    else {
                        int q = qi - 3;
                        float pre = 0.f;
                        #pragma unroll
                        for (int k = 0; k < 9; ++k)
                            if (k >= 4 - q) pre += w1s[c1*9 + k] * xs[w*8 + q - 4 + k];
                        float rv = pre * s1s[c1] + e1s[c1];
                        val = (rv > 0.f ? rv : 0.f) - gl;
                    }
                } else {
                    float gl = g_r1[(b*64 + c1)*S_ + t + 51 + qi];
                    if (qi >= 4) val = -gl;
                    else {
                        int q = 46 + qi;
                        float pre = 0.f;
                        #pragma unroll
                        for (int k = 0; k < 9; ++k)
                            if (k <= 53 - q) pre += w1s[c1*9 + k] * xs[32 + w*8 + qi + k];
                        float rv = pre * s1s[c1] + e1s[c1];
                        val = (rv > 0.f ? rv : 0.f) - gl;
                    }
                }
            }
            dstage[s] = val;
        }
        __syncthreads();

        // ---- 3) conv2 correction -> stage3 ----
        {
            const int c2 = tid & 31, side = (tid >> 5) & 1, w = tid >> 6;
            const int t = t0 + w;
            float acc[7];
            #pragma unroll
            for (int p = 0; p < 7; ++p) acc[p] = 0.f;

            for (int c1 = 0; c1 < 64; ++c1) {
                const float* dp = dstage + ((w*2 + side)*64 + c1)*8;
                float4 A = *(const float4*)dp;
                float4 Bv = *(const float4*)(dp + 4);
                float d[8] = {A.x, A.y, A.z, A.w, Bv.x, Bv.y, Bv.z, Bv.w};
                const float* wp = w2s + c1*224 + c2;
                float wk[7];
                #pragma unroll
                for (int k = 0; k < 7; ++k) wk[k] = wp[k*32];
                if (side == 0) {
                    #pragma unroll
                    for (int p = 0; p < 7; ++p)
                        #pragma unroll
                        for (int k = 0; k < 7; ++k)
                            if (k + p <= 6) acc[p] += wk[k] * d[p + k];
                } else {
                    #pragma unroll
                    for (int p = 0; p < 7; ++p)
                        #pragma unroll
                        for (int k = 0; k < 7; ++k)
                            if (k >= 6 - p) acc[p] += wk[k] * d[p + k - 6];
                }
            }

            const float s2v = s2s[c2];
            float* sp = stage3 + ((w*2 + side)*32 + c2)*12;
            const float* gpb = g_r2p + ((size_t)b*S_ + t)*32 + c2;
            if (side == 0) {
                #pragma unroll
                for (int p = 0; p < 7; ++p) {
                    float gpre = gpb[(p + 2)*32];
                    float pre = gpre + s2v * acc[p];
                    sp[2 + p] = (pre > 0.f ? pre : 0.f) - (gpre > 0.f ? gpre : 0.f);
                }
                float e0 = gpb[0], e1v = gpb[32];
                sp[0] = -(e0 > 0.f ? e0 : 0.f);
                sp[1] = -(e1v > 0.f ? e1v : 0.f);
            } else {
                #pragma unroll
                for (int p = 0; p < 7; ++p) {
                    float gpre = gpb[(45 + p)*32];
                    float pre = gpre + s2v * acc[p];
                    sp[p] = (pre > 0.f ? pre : 0.f) - (gpre > 0.f ? gpre : 0.f);
                }
                float e0 = gpb[52*32], e1v = gpb[53*32];
                sp[7] = -(e0 > 0.f ? e0 : 0.f);
                sp[8] = -(e1v > 0.f ? e1v : 0.f);
            }
            sp[9] = 0.f; sp[10] = 0.f; sp[11] = 0.f;
        }
        __syncthreads();

        // ---- 4) conv3 correction + interior sums ----
        if (tid < 128) {
            const int c3 = tid & 15, ws = tid >> 4;
            const int side = ws & 1, w = ws >> 1;
            const int t = t0 + w;
            float acc[9];
            #pragma unroll
            for (int p = 0; p < 9; ++p) acc[p] = 0.f;

            for (int c2 = 0; c2 < 32; ++c2) {
                const float* dp = stage3 + (ws*32 + c2)*12;
                float4 A = *(const float4*)dp;
                float4 Bv = *(const float4*)(dp + 4);
                float C = dp[8];
                float d[9] = {A.x, A.y, A.z, A.w, Bv.x, Bv.y, Bv.z, Bv.w, C};
                const float* wp = w3s + c2*80 + c3;
                float wk[5];
                #pragma unroll
                for (int k = 0; k < 5; ++k) wk[k] = wp[k*16];
                if (side == 0) {
                    #pragma unroll
                    for (int p = 0; p < 9; ++p)
                        #pragma unroll
                        for (int k = 0; k < 5; ++k)
                            if (p + k <= 8) acc[p] += wk[k] * d[p + k];
                } else {
                    #pragma unroll
                    for (int p = 0; p < 9; ++p)
                        #pragma unroll
                        for (int k = 0; k < 5; ++k)
                            if (k >= 4 - p) acc[p] += wk[k] * d[p + k - 4];
                }
            }

            float sum = 0.f;
            const float s3v = s3s[c3];
            const float* rp = g_r3p + ((size_t)b*S_ + t)*16 + c3;
            #pragma unroll
            for (int j = 0; j < 9; ++j) {
                int P = side ? 41 + j : j;
                float pre = rp[P*16] + s3v * acc[j];
                sum += pre > 0.f ? pre : 0.f;
            }
            fbuf[ws*16 + c3] = sum;
        } else {
            const int tt = tid - 128;
            const int c3 = tt & 15, ws = tt >> 4;
            const int side = ws & 1, w = ws >> 1;
            const int t = t0 + w;
            const float* rp = g_r3p + ((size_t)b*S_ + t + 9 + side*16)*16 + c3;
            float sum = 0.f;
            #pragma unroll
            for (int i = 0; i < 16; ++i) {
                float g = rp[i*16];
                sum += g > 0.f ? g : 0.f;
            }
            fbuf[128 + ws*16 + c3] = sum;
        }
        __syncthreads();

        // ---- 5) combine -> feats ----
        if (tid < 64) {
            int w = tid >> 4, c3 = tid & 15;
            float sum = fbuf[(w*2    )*16 + c3] + fbuf[(w*2 + 1)*16 + c3]
                      + fbuf[128 + (w*2)*16 + c3] + fbuf[128 + (w*2 + 1)*16 + c3];
            g_feats[(b*T_ + t0 + w)*16 + c3] = sum * 0.02f;
        }
        __syncthreads();
    }
}

// ---------------- pre-GEMM (layer0 input projection) + flag reset ----------------
__global__ void __launch_bounds__(256) gemm_pre16(
    const float* __restrict__ wih, const float* __restrict__ bi, const float* __restrict__ bh)
{
    __shared__ float ws[16*256];
    __shared__ float ft[16*16];
    __shared__ float bs[256];
    int tid = threadIdx.x;
    if (blockIdx.x == 0 && tid < B_) { g_flag0[tid] = 0; g_flag1[tid] = 0; }
    for (int i = tid; i < 4096; i += 256) { int j = i >> 4, k = i & 15; ws[k*256 + j] = wih[i]; }
    bs[tid] = bi[tid] + bh[tid];
    int r0 = blockIdx.x * 16;
    ft[tid] = g_feats[r0*16 + tid];
    __syncthreads();
    float acc[16];
    #pragma unroll
    for (int r = 0; r < 16; ++r) acc[r] = bs[tid];
    #pragma unroll
    for (int k = 0; k < 16; ++k) {
        float w = ws[k*256 + tid];
        #pragma unroll
        for (int r = 0; r < 16; ++r) acc[r] += w * ft[r*16 + k];
    }
    #pragma unroll
    for (int r = 0; r < 16; ++r) g_pre[(r0 + r)*256 + tid] = acc[r];
}

// ---------------- 3-stage pipelined LSTM ----------------
__device__ __forceinline__ float sigf(float x)  { return __fdividef(1.f, 1.f + __expf(-x)); }
__device__ __forceinline__ float tanhq(float x) { return __fdividef(2.f, 1.f + __expf(-2.f*x)) - 1.f; }

__device__ __forceinline__ unsigned long long pk2(float a, float b) {
    unsigned long long r;
    asm("mov.b64 %0, {%1, %2};" : "=l"(r) : "f"(a), "f"(b));
    return r;
}
__device__ __forceinline__ void fma2(unsigned long long& d,
                                     unsigned long long a, unsigned long long b) {
    asm("fma.rn.f32x2 %0, %1, %2, %0;" : "+l"(d) : "l"(a), "l"(b));
}
__device__ __forceinline__ float2 upk2(unsigned long long v) {
    float2 f;
    asm("mov.b64 {%0, %1}, %2;" : "=f"(f.x), "=f"(f.y) : "l"(v));
    return f;
}
__device__ __forceinline__ void relstore(int* p, int v) {
    asm volatile("st.release.gpu.global.s32 [%0], %1;" :: "l"(p), "r"(v) : "memory");
}
__device__ __forceinline__ int acqload(const int* p) {
    int v;
    asm volatile("ld.acquire.gpu.global.s32 %0, [%1];" : "=r"(v) : "l"(p) : "memory");
    return v;
}
__device__ __forceinline__ float gact(int g, float v) {
    return ((g >> 6) == 2) ? tanhq(v) : sigf(v);   // gate order: i, f, g(tanh), o
}

// grid 48: 0..15 producers (L0 rec), 16..31 mid (wih1 GEMM), 32..47 consumers (L1 rec)
__global__ void __launch_bounds__(256, 1) lstm_fused(
    const float* __restrict__ whh0, const float* __restrict__ wih1,
    const float* __restrict__ whh1,
    const float* __restrict__ bih1, const float* __restrict__ bhh1)
{
    __shared__ __align__(16) float hsm[64];
    __shared__ float acts[256];
    __shared__ __align__(16) float h1c[512];     // mid: 8-step h1 chunk
    const int tid = threadIdx.x;

    if (blockIdx.x < 16) {
        // ============ producer: layer0 recurrence -> h1 stream ============
        const int b = blockIdx.x;
        unsigned long long w0[32];
        {
            const float4* r0 = (const float4*)(whh0 + tid*64);
            #pragma unroll
            for (int q = 0; q < 16; ++q) {
                float4 a = r0[q]; w0[2*q] = pk2(a.x, a.y); w0[2*q+1] = pk2(a.z, a.w);
            }
        }
        const float* preB = g_pre + (size_t)b * T_ * 256;
        float* h1B = g_h1 + (size_t)b * T_ * 64;
        float cst = 0.f;
        if (tid < 64) hsm[tid] = 0.f;
        float pg  = preB[tid];                   // gates0(0) pre-act (h1(-1)=0)
        float pcn = preB[256 + tid];             // pre0(1)
        acts[tid] = gact(tid, pg);
        __syncthreads();

        for (int t = 0; t < T_; ++t) {
            // phase 2: state update + h1 publish
            if (tid < 64) {
                float c_ = acts[64 + tid]*cst + acts[tid]*acts[128 + tid];
                cst = c_;
                float h = acts[192 + tid]*tanhq(c_);
                hsm[tid] = h;
                h1B[t*64 + tid] = h;
            } else if (tid == 64 && (t & 3) == 0 && t) {
                relstore(&g_flag0[b], t);        // h1(0..t-1) visible
            }
            __syncthreads();
            // phase 3: whh0 dot with h1(t)
            unsigned long long a0 = 0ull, a1 = 0ull;
            const ulonglong2* hp = (const ulonglong2*)hsm;
            #pragma unroll
            for (int q = 0; q < 16; ++q) {
                ulonglong2 hv = hp[q];
                fma2(a0, w0[2*q],   hv.x);
                fma2(a1, w0[2*q+1], hv.y);
            }
            float2 f0 = upk2(a0), f1 = upk2(a1);
            pg = pcn + (f0.x + f0.y) + (f1.x + f1.y);   // gates0(t+1) pre-act
            acts[tid] = gact(tid, pg);
            int tn = (t + 2 < T_) ? t + 2 : T_ - 1;
            pcn = preB[tn*256 + tid];
            __syncthreads();
        }
        if (tid == 0) relstore(&g_flag0[b], T_);
    } else if (blockIdx.x < 32) {
        // ============ mid: pre1 = wih1 @ h1 + bias (chunked GEMM, off critical path) ============
        const int b = blockIdx.x - 16;
        unsigned long long w1[32];
        {
            const float4* r1 = (const float4*)(wih1 + tid*64);
            #pragma unroll
            for (int q = 0; q < 16; ++q) {
                float4 a = r1[q]; w1[2*q] = pk2(a.x, a.y); w1[2*q+1] = pk2(a.z, a.w);
            }
        }
        const float bias1v = bih1[tid] + bhh1[tid];
        const float* h1B = g_h1 + (size_t)b * T_ * 64;
        float* pre1B = g_pre1 + (size_t)b * T_ * 256;
        int flagv = 0;

        for (int c = 0; c < T_/8; ++c) {
            int need = c*8 + 8;
            if (flagv < need) {
                do { flagv = acqload(&g_flag0[b]); if (flagv < need) __nanosleep(128); }
                while (flagv < need);
            }
            for (int i = tid; i < 512; i += 256) h1c[i] = h1B[c*512 + i];
            __syncthreads();
            #pragma unroll
            for (int j = 0; j < 8; ++j) {
                unsigned long long a0 = 0ull, a1 = 0ull;
                const ulonglong2* hp = (const ulonglong2*)(h1c + j*64);
                #pragma unroll
                for (int q = 0; q < 16; ++q) {
                    ulonglong2 hv = hp[q];
                    fma2(a0, w1[2*q],   hv.x);
                    fma2(a1, w1[2*q+1], hv.y);
                }
                float2 f0 = upk2(a0), f1 = upk2(a1);
                pre1B[(c*8 + j)*256 + tid] = bias1v + (f0.x + f0.y) + (f1.x + f1.y);
            }
            __syncthreads();
            if (tid == 0) relstore(&g_flag1[b], c*8 + 8);
        }
    } else {
        // ============ consumer: layer1 recurrence ============
        const int b = blockIdx.x - 32;
        unsigned long long w2r[32];
        {
            const float4* r2 = (const float4*)(whh1 + tid*64);
            #pragma unroll
            for (int q = 0; q < 16; ++q) {
                float4 a = r2[q]; w2r[2*q] = pk2(a.x, a.y); w2r[2*q+1] = pk2(a.z, a.w);
            }
        }
        const float* pre1B = g_pre1 + (size_t)b * T_ * 256;
        float* hB = g_h + (size_t)b * T_ * 64;
        float cst = 0.f;
        int flagv = 0;
        if (tid < 64) hsm[tid] = 0.f;
        while (flagv < 2) { flagv = acqload(&g_flag1[b]); if (flagv < 2) __nanosleep(256); }
        float cg  = pre1B[tid];                  // gates1(0) pre-act (h2(-1)=0)
        float p1n = pre1B[256 + tid];            // pre1(1)
        acts[tid] = gact(tid, cg);
        __syncthreads();

        for (int t = 0; t < T_; ++t) {
            // phase 2: state update + h2 store
            if (tid < 64) {
                float c_ = acts[64 + tid]*cst + acts[tid]*acts[128 + tid];
                cst = c_;
                float h = acts[192 + tid]*tanhq(c_);
                hsm[tid] = h;
                hB[t*64 + tid] = h;
            }
            __syncthreads();
            // phase 3: whh1 dot with h2(t)
            unsigned long long a0 = 0ull, a1 = 0ull;
            const ulonglong2* hp = (const ulonglong2*)hsm;
            #pragma unroll
            for (int q = 0; q < 16; ++q) {
                ulonglong2 hv = hp[q];
                fma2(a0, w2r[2*q],   hv.x);
                fma2(a1, w2r[2*q+1], hv.y);
            }
            float2 f0 = upk2(a0), f1 = upk2(a1);
            cg = p1n + (f0.x + f0.y) + (f1.x + f1.y);   // gates1(t+1) pre-act
            acts[tid] = gact(tid, cg);
            int tn = (t + 2 < T_) ? t + 2 : T_ - 1;
            if (flagv < tn + 1) {
                do { flagv = acqload(&g_flag1[b]); if (flagv < tn + 1) __nanosleep(64); }
                while (flagv < tn + 1);
            }
            p1n = pre1B[tn*256 + tid];
            __syncthreads();
        }
    }
}

// ---------------- FC head ----------------
__global__ void __launch_bounds__(256) fc_kernel(
    const float* __restrict__ w1, const float* __restrict__ b1,
    const float* __restrict__ w2, const float* __restrict__ b2,
    float* __restrict__ out)
{
    __shared__ __align__(16) float w1s[2048];
    __shared__ float w2s[64];
    __shared__ float b1s[32];
    int tid = threadIdx.x;
    for (int i = tid; i < 2048; i += 256) w1s[i] = w1[i];
    if (tid < 64) w2s[tid] = w2[tid];
    if (tid < 32) b1s[tid] = b1[tid];
    __syncthreads();

    int gid = blockIdx.x*256 + tid;
    const float4* h4p = (const float4*)(g_h + (size_t)gid * 64);
    float4 h[16];
    #pragma unroll
    for (int q = 0; q < 16; ++q) h[q] = h4p[q];

    float l0 = b2[0], l1 = b2[1];
    #pragma unroll
    for (int i = 0; i < 32; ++i) {
        float acc = b1s[i];
        const float4* wr = (const float4*)(w1s + i*64);
        #pragma unroll
        for (int q = 0; q < 16; ++q) {
            float4 w4 = wr[q];
            acc += w4.x*h[q].x + w4.y*h[q].y + w4.z*h[q].z + w4.w*h[q].w;
        }
        acc = acc > 0.f ? acc : 0.f;
        l0 += w2s[i] * acc;
        l1 += w2s[32 + i] * acc;
    }
    ((float2*)out)[gid] = make_float2(l0, l1);
}

// ---------------- launch ----------------
extern "C" void kernel_launch(void* const* d_in, const int* in_sizes, int n_in,
                              void* d_out, int out_size)
{
    const float* x     = (const float*)d_in[0];
    const float* c1w   = (const float*)d_in[1];
    const float* c1b   = (const float*)d_in[2];
    const float* bn1g  = (const float*)d_in[3];
    const float* bn1b  = (const float*)d_in[4];
    const float* bn1m  = (const float*)d_in[5];
    const float* bn1v  = (const float*)d_in[6];
    const float* c2w   = (const float*)d_in[7];
    const float* c2b   = (const float*)d_in[8];
    const float* bn2g  = (const float*)d_in[9];
    const float* bn2b  = (const float*)d_in[10];
    const float* bn2m  = (const float*)d_in[11];
    const float* bn2v  = (const float*)d_in[12];
    const float* c3w   = (const float*)d_in[13];
    const float* c3b   = (const float*)d_in[14];
    const float* bn3g  = (const float*)d_in[15];
    const float* bn3b  = (const float*)d_in[16];
    const float* bn3m  = (const float*)d_in[17];
    const float* bn3v  = (const float*)d_in[18];
    const float* wih0  = (const float*)d_in[19];
    const float* whh0  = (const float*)d_in[20];
    const float* bih0  = (const float*)d_in[21];
    const float* bhh0  = (const float*)d_in[22];
    const float* wih1  = (const float*)d_in[23];
    const float* whh1  = (const float*)d_in[24];
    const float* bih1  = (const float*)d_in[25];
    const float* bhh1  = (const float*)d_in[26];
    const float* fc1w  = (const float*)d_in[27];
    const float* fc1b  = (const float*)d_in[28];
    const float* fc2w  = (const float*)d_in[29];
    const float* fc2b  = (const float*)d_in[30];

    cudaFuncSetAttribute(conv2g_kernel, cudaFuncAttributeMaxDynamicSharedMemorySize,
                         C2G_SMEM_FLOATS * 4);
    cudaFuncSetAttribute(bnd_fused_kernel, cudaFuncAttributeMaxDynamicSharedMemorySize,
                         BND_SMEM_FLOATS * 4);

    // Phase A: global conv stack
    conv1g_kernel<<<dim3(9, B_), 256>>>(x, c1w, c1b, bn1g, bn1b, bn1m, bn1v);
    conv2g_kernel<<<dim3(33, B_), 256, C2G_SMEM_FLOATS * 4>>>(c2w, c2b, bn2g, bn2b, bn2m, bn2v);
    conv3g_kernel<<<dim3(33, B_), 256>>>(c3w, c3b, bn3g, bn3b, bn3m, bn3v);

    // Phase B: persistent fused boundary corrections -> feats
    bnd_fused_kernel<<<NCTA, 256, BND_SMEM_FLOATS * 4>>>(
        x, c1w, c1b, bn1g, bn1b, bn1m, bn1v,
        c2w, bn2g, bn2v, c3w, bn3g, bn3v);

    // layer0 input projection (+ flag reset)
    gemm_pre16<<<(B_ * T_) / 16, 256>>>(wih0, bih0, bhh0);

    // 3-stage pipelined LSTM (producer / mid-GEMM / consumer)
    lstm_fused<<<48, 256>>>(whh0, wih1, whh1, bih1, bhh1);

    // FC head
    fc_kernel<<<(B_ * T_) / 256, 256>>>(fc1w, fc1b, fc2w, fc2b, (float*)d_out);
}

// round 12
// speedup vs baseline: 1.9027x; 1.0963x over previous
#include <cuda_runtime.h>

#define EPSV 1e-5f
#define B_   16
#define T_   2048
#define S_   2112        // padded stride for global conv buffers

// Global buffers:
__device__ __align__(128) float g_r1 [B_*64*S_];
__device__ __align__(128) float g_r2p[B_*S_*32];
__device__ __align__(128) float g_r3p[B_*S_*16];
__device__ __align__(128) float g_feats[B_*T_*16];
__device__ __align__(128) float g_h1  [B_*T_*64];    // h1 stream (producer -> mid)
__device__ __align__(128) float g_pre1[B_*T_*256];   // layer1 input projection (mid -> consumer)
__device__ __align__(128) float g_h[B_*T_*64];       // h2 (fc input)
__device__ int g_done[B_*8];                         // bnd chunk arrival counters (64 each)
__device__ int g_flag0[B_];
__device__ int g_flag1[B_];

// ======================= Phase A: global conv stack =======================
// XP[i] = x[i-49] for 49<=i<=2096 else 0.

__global__ void __launch_bounds__(256) conv1g_kernel(
    const float* __restrict__ x,
    const float* __restrict__ c1w, const float* __restrict__ c1b,
    const float* __restrict__ g1, const float* __restrict__ b1p,
    const float* __restrict__ m1, const float* __restrict__ v1)
{
    __shared__ float xw[264];
    __shared__ float w1s[576];
    __shared__ float s1[64], e1[64];
    const int tid = threadIdx.x;
    const int b = blockIdx.y;
    const int u0 = blockIdx.x * 256;
    if (blockIdx.x == 0 && b == 0) {             // reset pipeline flags each replay
        if (tid < B_*8) g_done[tid] = 0;
        else if (tid < B_*8 + B_) g_flag0[tid - B_*8] = 0;
        else if (tid < B_*8 + 2*B_) g_flag1[tid - B_*8 - B_] = 0;
    }
    for (int j = tid; j < 264; j += 256) {
        int i = u0 - 9 + j;                      // XP index
        xw[j] = (i >= 49 && i <= 2096) ? x[b*2048 + i - 49] : 0.f;
    }
    for (int i = tid; i < 576; i += 256) w1s[i] = c1w[i];
    if (tid < 64) {
        float s = g1[tid] * rsqrtf(v1[tid] + EPSV);
        s1[tid] = s; e1[tid] = (c1b[tid] - m1[tid]) * s + b1p[tid];
    }
    __syncthreads();
    int u = u0 + tid;
    if (u < 2107) {
        float xv[9];
        #pragma unroll
        for (int k = 0; k < 9; ++k) xv[k] = xw[tid + k];
        for (int c = 0; c < 64; ++c) {
            float acc = 0.f;
            #pragma unroll
            for (int k = 0; k < 9; ++k) acc += w1s[c*9 + k] * xv[k];
            float r = acc * s1[c] + e1[c];
            g_r1[(b*64 + c)*S_ + u] = r > 0.f ? r : 0.f;
        }
    }
}

#define C2G_SMEM_FLOATS (14336 + 64*72 + 64)
__global__ void __launch_bounds__(256) conv2g_kernel(
    const float* __restrict__ c2w, const float* __restrict__ c2b,
    const float* __restrict__ g2, const float* __restrict__ b2p,
    const float* __restrict__ m2, const float* __restrict__ v2)
{
    extern __shared__ float sm[];
    float* w2s = sm;               // [(c1*7+k)*32 + c2]
    float* r1t = sm + 14336;       // [64][72]
    float* s2  = r1t + 4608;
    float* e2  = s2 + 32;
    const int tid = threadIdx.x;
    const int b = blockIdx.y;
    const int u0 = blockIdx.x * 64;

    for (int i = tid; i < 14336; i += 256) {
        int c2 = i / 448; int r = i % 448; int c1 = r / 7; int k = r % 7;
        w2s[(c1*7 + k)*32 + c2] = c2w[i];
    }
    if (tid < 32) {
        float s = g2[tid] * rsqrtf(v2[tid] + EPSV);
        s2[tid] = s; e2[tid] = (c2b[tid] - m2[tid]) * s + b2p[tid];
    }
    for (int f = tid; f < 64*70; f += 256) {
        int c1 = f / 70, i = f - c1*70;
        int u = u0 + i;
        r1t[c1*72 + i] = (u <= 2106) ? g_r1[(b*64 + c1)*S_ + u] : 0.f;
    }
    __syncthreads();

    const int c2 = tid & 31, slot = tid >> 5;   // 8 slots x 8 positions
    float acc[8];
    #pragma unroll
    for (int j = 0; j < 8; ++j) acc[j] = 0.f;
    for (int c1 = 0; c1 < 64; ++c1) {
        const float* rp = r1t + c1*72 + slot*8;
        float v[14];
        #pragma unroll
        for (int i = 0; i < 14; ++i) v[i] = rp[i];
        const float* wp = w2s + c1*224 + c2;
        #pragma unroll
        for (int k = 0; k < 7; ++k) {
            float wv = wp[k*32];
            #pragma unroll
            for (int j = 0; j < 8; ++j) acc[j] += wv * v[k + j];
        }
    }
    float ss = s2[c2], bb = e2[c2];
    #pragma unroll
    for (int j = 0; j < 8; ++j) {
        int u = u0 + slot*8 + j;
        if (u <= 2100)
            g_r2p[((size_t)b*S_ + u)*32 + c2] = acc[j] * ss + bb;   // PRE-act, chan-last
    }
}

__global__ void __launch_bounds__(256) conv3g_kernel(
    const float* __restrict__ c3w, const float* __restrict__ c3b,
    const float* __restrict__ g3, const float* __restrict__ b3p,
    const float* __restrict__ m3, const float* __restrict__ v3)
{
    __shared__ float w3s[2560];      // [(c2*5+k)*16 + c3]
    __shared__ float r2t[32*72];
    __shared__ float s3[16], e3[16];
    const int tid = threadIdx.x;
    const int b = blockIdx.y;
    const int u0 = blockIdx.x * 64;

    for (int i = tid; i < 2560; i += 256) {
        int c3 = i / 160; int r = i % 160; int cc = r / 5; int k = r % 5;
        w3s[(cc*5 + k)*16 + c3] = c3w[i];
    }
    if (tid < 16) {
        float s = g3[tid] * rsqrtf(v3[tid] + EPSV);
        s3[tid] = s; e3[tid] = (c3b[tid] - m3[tid]) * s + b3p[tid];
    }
    // coalesced: cc fastest
    for (int f = tid; f < 32*68; f += 256) {
        int cc = f & 31, i = f >> 5;
        int u = u0 + i;
        float g = (u <= 2100) ? g_r2p[((size_t)b*S_ + u)*32 + cc] : 0.f;
        r2t[cc*72 + i] = g > 0.f ? g : 0.f;      // ReLU on load
    }
    __syncthreads();

    const int c3 = tid & 15, slot = tid >> 4;   // 16 slots x 4 positions
    float acc[4] = {0.f, 0.f, 0.f, 0.f};
    for (int cc = 0; cc < 32; ++cc) {
        const float* rp = r2t + cc*72 + slot*4;
        float v[8];
        #pragma unroll
        for (int i = 0; i < 8; ++i) v[i] = rp[i];
        const float* wp = w3s + cc*80 + c3;
        #pragma unroll
        for (int k = 0; k < 5; ++k) {
            float wv = wp[k*16];
            #pragma unroll
            for (int j = 0; j < 4; ++j) acc[j] += wv * v[k + j];
        }
    }
    float ss = s3[c3], bb = e3[c3];
    #pragma unroll
    for (int j = 0; j < 4; ++j) {
        int u = u0 + slot*4 + j;
        if (u <= 2096)
            g_r3p[((size_t)b*S_ + u)*16 + c3] = acc[j] * ss + bb;   // PRE-act, chan-last
    }
}

// ======================= Fused Phase B + LSTM (single launch, overlap by co-residency) =====
// grid 1072: blocks 0..15 producers, 16..31 mid, 32..47 consumers, 48..1071 bnd.
// bnd CTAs never wait; lstm CTAs sit at low indices -> wave-1 resident. Deadlock-free.
#define BND_SMEM_FLOATS (14336 + 2560 + 576 + 176 + 64 + 4096 + 3072 + 256)
#define NBND  1024
#define NGRP  8

__device__ __forceinline__ float sigf(float x)  { return __fdividef(1.f, 1.f + __expf(-x)); }
__device__ __forceinline__ float tanhq(float x) { return __fdividef(2.f, 1.f + __expf(-2.f*x)) - 1.f; }

__device__ __forceinline__ unsigned long long pk2(float a, float b) {
    unsigned long long r;
    asm("mov.b64 %0, {%1, %2};" : "=l"(r) : "f"(a), "f"(b));
    return r;
}
__device__ __forceinline__ void fma2(unsigned long long& d,
                                     unsigned long long a, unsigned long long b) {
    asm("fma.rn.f32x2 %0, %1, %2, %0;" : "+l"(d) : "l"(a), "l"(b));
}
__device__ __forceinline__ float2 upk2(unsigned long long v) {
    float2 f;
    asm("mov.b64 {%0, %1}, %2;" : "=f"(f.x), "=f"(f.y) : "l"(v));
    return f;
}
__device__ __forceinline__ void relstore(int* p, int v) {
    asm volatile("st.release.gpu.global.s32 [%0], %1;" :: "l"(p), "r"(v) : "memory");
}
__device__ __forceinline__ int acqload(const int* p) {
    int v;
    asm volatile("ld.acquire.gpu.global.s32 %0, [%1];" : "=r"(v) : "l"(p) : "memory");
    return v;
}
__device__ __forceinline__ float gact(int g, float v) {
    return ((g >> 6) == 2) ? tanhq(v) : sigf(v);   // gate order: i, f, g(tanh), o
}

__global__ void __launch_bounds__(256, 2) bnd_lstm_kernel(
    const float* __restrict__ x,
    const float* __restrict__ c1w, const float* __restrict__ c1b,
    const float* __restrict__ g1, const float* __restrict__ b1p,
    const float* __restrict__ m1, const float* __restrict__ v1,
    const float* __restrict__ c2w,
    const float* __restrict__ g2, const float* __restrict__ v2,
    const float* __restrict__ c3w,
    const float* __restrict__ g3, const float* __restrict__ v3,
    const float* __restrict__ wih0, const float* __restrict__ whh0,
    const float* __restrict__ bih0, const float* __restrict__ bhh0,
    const float* __restrict__ wih1, const float* __restrict__ whh1,
    const float* __restrict__ bih1, const float* __restrict__ bhh1)
{
    extern __shared__ float sm[];
    const int tid = threadIdx.x;

    if (blockIdx.x >= 48) {
        // ==================== bnd: boundary corrections -> feats ====================
        float* w2s    = sm;               // 14336
        float* w3s    = sm + 14336;       // 2560
        float* w1s    = sm + 16896;       // 576
        float* s1s    = sm + 17472;       // 64
        float* e1s    = sm + 17536;       // 64
        float* s2s    = sm + 17600;       // 32
        float* s3s    = sm + 17632;       // 16 (+pad to 17648)
        float* xs     = sm + 17648;       // 64
        float* dstage = sm + 17712;       // 4096
        float* stage3 = sm + 21808;       // 3072
        float* fbuf   = sm + 24880;       // 256

        const int bid = blockIdx.x - 48;
        const int b  = bid >> 6;          // batch
        const int jj = bid & 63;          // CTA slot within batch

        for (int i = tid; i < 14336; i += 256) {
            int c2 = i / 448; int r = i % 448; int c1 = r / 7; int k = r % 7;
            w2s[(c1*7 + k)*32 + c2] = c2w[i];
        }
        for (int i = tid; i < 2560; i += 256) {
            int c3 = i / 160; int r = i % 160; int cc = r / 5; int k = r % 5;
            w3s[(cc*5 + k)*16 + c3] = c3w[i];
        }
        for (int i = tid; i < 576; i += 256) w1s[i] = c1w[i];
        if (tid < 64) {
            float s = g1[tid] * rsqrtf(v1[tid] + EPSV);
            s1s[tid] = s; e1s[tid] = (c1b[tid] - m1[tid]) * s + b1p[tid];
        } else if (tid < 96) {
            int c = tid - 64;
            s2s[c] = g2[c] * rsqrtf(v2[c] + EPSV);
        } else if (tid < 112) {
            int c = tid - 96;
            s3s[c] = g3[c] * rsqrtf(v3[c] + EPSV);
        }
        __syncthreads();

        for (int it = 0; it < NGRP; ++it) {
            const int t0 = ((it << 6) + jj) * 4;

            // ---- 1) stage x values ----
            if (tid < 64) {
                int w = tid >> 4, r = tid & 15;
                int side = r >> 3, j = r & 7;
                int i = t0 + w + (side ? 42 + j : j);
                float v = (i >= 49 && i <= 2096) ? x[b*2048 + i - 49] : 0.f;
                xs[side*32 + w*8 + j] = v;
            }
            __syncthreads();

            // ---- 2) stage delta1 ----
            for (int s = tid; s < 4096; s += 256) {
                int qi = s & 7, c1 = (s >> 3) & 63, side = (s >> 9) & 1, w = s >> 10;
                int t = t0 + w;
                float val = 0.f;
                if (qi < 7) {
                    if (side == 0) {
                        float gl = g_r1[(b*64 + c1)*S_ + t + qi + 2];
                        if (qi < 3) val = -gl;
                        else {
                            int q = qi - 3;
                            float pre = 0.f;
                            #pragma unroll
                            for (int k = 0; k < 9; ++k)
                                if (k >= 4 - q) pre += w1s[c1*9 + k] * xs[w*8 + q - 4 + k];
                            float rv = pre * s1s[c1] + e1s[c1];
                            val = (rv > 0.f ? rv : 0.f) - gl;
                        }
                    } else {
                        float gl = g_r1[(b*64 + c1)*S_ + t + 51 + qi];
                        if (qi >= 4) val = -gl;
                        else {
                            int q = 46 + qi;
                            float pre = 0.f;
                            #pragma unroll
                            for (int k = 0; k < 9; ++k)
                                if (k <= 53 - q) pre += w1s[c1*9 + k] * xs[32 + w*8 + qi + k];
                            float rv = pre * s1s[c1] + e1s[c1];
                            val = (rv > 0.f ? rv : 0.f) - gl;
                        }
                    }
                }
                dstage[s] = val;
            }
            __syncthreads();

            // ---- 3) conv2 correction -> stage3 ----
            {
                const int c2 = tid & 31, side = (tid >> 5) & 1, w = tid >> 6;
                const int t = t0 + w;
                float acc[7];
                #pragma unroll
                for (int p = 0; p < 7; ++p) acc[p] = 0.f;

                for (int c1 = 0; c1 < 64; ++c1) {
                    const float* dp = dstage + ((w*2 + side)*64 + c1)*8;
                    float4 A = *(const float4*)dp;
                    float4 Bv = *(const float4*)(dp + 4);
                    float d[8] = {A.x, A.y, A.z, A.w, Bv.x, Bv.y, Bv.z, Bv.w};
                    const float* wp = w2s + c1*224 + c2;
                    float wk[7];
                    #pragma unroll
                    for (int k = 0; k < 7; ++k) wk[k] = wp[k*32];
                    if (side == 0) {
                        #pragma unroll
                        for (int p = 0; p < 7; ++p)
                            #pragma unroll
                            for (int k = 0; k < 7; ++k)
                                if (k + p <= 6) acc[p] += wk[k] * d[p + k];
                    } else {
                        #pragma unroll
                        for (int p = 0; p < 7; ++p)
                            #pragma unroll
                            for (int k = 0; k < 7; ++k)
                                if (k >= 6 - p) acc[p] += wk[k] * d[p + k - 6];
                    }
                }

                const float s2v = s2s[c2];
                float* sp = stage3 + ((w*2 + side)*32 + c2)*12;
                const float* gpb = g_r2p + ((size_t)b*S_ + t)*32 + c2;
                if (side == 0) {
                    #pragma unroll
                    for (int p = 0; p < 7; ++p) {
                        float gpre = gpb[(p + 2)*32];
                        float pre = gpre + s2v * acc[p];
                        sp[2 + p] = (pre > 0.f ? pre : 0.f) - (gpre > 0.f ? gpre : 0.f);
                    }
                    float e0 = gpb[0], e1v = gpb[32];
                    sp[0] = -(e0 > 0.f ? e0 : 0.f);
                    sp[1] = -(e1v > 0.f ? e1v : 0.f);
                } else {
                    #pragma unroll
                    for (int p = 0; p < 7; ++p) {
                        float gpre = gpb[(45 + p)*32];
                        float pre = gpre + s2v * acc[p];
                        sp[p] = (pre > 0.f ? pre : 0.f) - (gpre > 0.f ? gpre : 0.f);
                    }
                    float e0 = gpb[52*32], e1v = gpb[53*32];
                    sp[7] = -(e0 > 0.f ? e0 : 0.f);
                    sp[8] = -(e1v > 0.f ? e1v : 0.f);
                }
                sp[9] = 0.f; sp[10] = 0.f; sp[11] = 0.f;
            }
            __syncthreads();

            // ---- 4) conv3 correction + interior sums ----
            if (tid < 128) {
                const int c3 = tid & 15, ws = tid >> 4;
                const int side = ws & 1, w = ws >> 1;
                const int t = t0 + w;
                float acc[9];
                #pragma unroll
                for (int p = 0; p < 9; ++p) acc[p] = 0.f;

                for (int c2 = 0; c2 < 32; ++c2) {
                    const float* dp = stage3 + (ws*32 + c2)*12;
                    float4 A = *(const float4*)dp;
                    float4 Bv = *(const float4*)(dp + 4);
                    float C = dp[8];
                    float d[9] = {A.x, A.y, A.z, A.w, Bv.x, Bv.y, Bv.z, Bv.w, C};
                    const float* wp = w3s + c2*80 + c3;
                    float wk[5];
                    #pragma unroll
                    for (int k = 0; k < 5; ++k) wk[k] = wp[k*16];
                    if (side == 0) {
                        #pragma unroll
                        for (int p = 0; p < 9; ++p)
                            #pragma unroll
                            for (int k = 0; k < 5; ++k)
                                if (p + k <= 8) acc[p] += wk[k] * d[p + k];
                    } else {
                        #pragma unroll
                        for (int p = 0; p < 9; ++p)
                            #pragma unroll
                            for (int k = 0; k < 5; ++k)
                                if (k >= 4 - p) acc[p] += wk[k] * d[p + k - 4];
                    }
                }

                float sum = 0.f;
                const float s3v = s3s[c3];
                const float* rp = g_r3p + ((size_t)b*S_ + t)*16 + c3;
                #pragma unroll
                for (int j = 0; j < 9; ++j) {
                    int P = side ? 41 + j : j;
                    float pre = rp[P*16] + s3v * acc[j];
                    sum += pre > 0.f ? pre : 0.f;
                }
                fbuf[ws*16 + c3] = sum;
            } else {
                const int tt = tid - 128;
                const int c3 = tt & 15, ws = tt >> 4;
                const int side = ws & 1, w = ws >> 1;
                const int t = t0 + w;
                const float* rp = g_r3p + ((size_t)b*S_ + t + 9 + side*16)*16 + c3;
                float sum = 0.f;
                #pragma unroll
                for (int i = 0; i < 16; ++i) {
                    float g = rp[i*16];
                    sum += g > 0.f ? g : 0.f;
                }
                fbuf[128 + ws*16 + c3] = sum;
            }
            __syncthreads();

            // ---- 5) combine -> feats, then signal chunk arrival ----
            if (tid < 64) {
                int w = tid >> 4, c3 = tid & 15;
                float sum = fbuf[(w*2    )*16 + c3] + fbuf[(w*2 + 1)*16 + c3]
                          + fbuf[128 + (w*2)*16 + c3] + fbuf[128 + (w*2 + 1)*16 + c3];
                g_feats[(b*T_ + t0 + w)*16 + c3] = sum * 0.02f;
            }
            __syncthreads();
            if (tid == 0) {
                __threadfence();
                atomicAdd(&g_done[b*8 + it], 1);
            }
        }
        return;
    }

    // ==================== LSTM roles (blocks 0..47) ====================
    float* hsm    = sm;          // 64
    float* acts   = sm + 64;     // 256
    float* featsm = sm + 320;    // 2*16
    float* h1c    = sm + 352;    // 512 (mid only)

    if (blockIdx.x < 16) {
        // ============ producer: layer0 recurrence + inline pre0 (feats consumed live) ============
        const int b = blockIdx.x;
        unsigned long long w0[32], w0i[8];
        {
            const float4* r0 = (const float4*)(whh0 + tid*64);
            #pragma unroll
            for (int q = 0; q < 16; ++q) {
                float4 a = r0[q]; w0[2*q] = pk2(a.x, a.y); w0[2*q+1] = pk2(a.z, a.w);
            }
            const float4* ri = (const float4*)(wih0 + tid*16);
            #pragma unroll
            for (int q = 0; q < 4; ++q) {
                float4 a = ri[q]; w0i[2*q] = pk2(a.x, a.y); w0i[2*q+1] = pk2(a.z, a.w);
            }
        }
        const float bias0v = bih0[tid] + bhh0[tid];
        const float* featsB = g_feats + (size_t)b * T_ * 16;
        float* h1B = g_h1 + (size_t)b * T_ * 64;
        float cst = 0.f;
        if (tid < 64) hsm[tid] = 0.f;

        // wait for first feats chunk from bnd
        if (tid == 0) {
            while (acqload(&g_done[b*8]) < 64) __nanosleep(1024);
        }
        __syncthreads();
        // stage feats(0), feats(1)
        if (tid < 8) {
            int w = tid >> 2, l = tid & 3;
            ((float4*)(featsm + w*16))[l] = ((const float4*)(featsB + w*16))[l];
        }
        __syncthreads();
        // gates0(0) = bias0 + wih0 . feats(0)
        float pg;
        {
            unsigned long long e0 = 0ull, e1 = 0ull;
            const ulonglong2* fq = (const ulonglong2*)featsm;
            #pragma unroll
            for (int q = 0; q < 4; ++q) {
                ulonglong2 fv = fq[q];
                fma2(e0, w0i[2*q],   fv.x);
                fma2(e1, w0i[2*q+1], fv.y);
            }
            float2 f0 = upk2(e0), f1 = upk2(e1);
            pg = bias0v + (f0.x + f0.y) + (f1.x + f1.y);
        }
        acts[tid] = gact(tid, pg);
        float4 r4;
        if (tid >= 128 && tid < 132) {
            r4 = ((const float4*)(featsB + 2*16))[tid - 128];   // feats(2)
        }
        __syncthreads();

        for (int t = 0; t < T_; ++t) {
            // phase 2: state update + h1 publish + feats staging
            if (tid < 64) {
                float c_ = acts[64 + tid]*cst + acts[tid]*acts[128 + tid];
                cst = c_;
                float h = acts[192 + tid]*tanhq(c_);
                hsm[tid] = h;
                h1B[t*64 + tid] = h;
            } else if (tid == 64 && (t & 3) == 0 && t) {
                relstore(&g_flag0[b], t);        // h1(0..t-1) visible
            } else if (tid >= 128 && tid < 132) {
                int l = tid - 128;
                ((float4*)(featsm + ((t + 2) & 1)*16))[l] = r4;   // feats(t+2) -> slot
                int nidx = t + 3;
                int idx = (nidx < T_) ? nidx : T_ - 1;
                if (nidx < T_ && (nidx & 255) == 0) {
                    int ck = nidx >> 8;
                    while (acqload(&g_done[b*8 + ck]) < 64) __nanosleep(256);
                }
                r4 = ((const float4*)(featsB + (size_t)idx*16))[l];
            }
            __syncthreads();
            // phase 3: whh0 dot with h1(t) + wih0 dot with feats(t+1)
            unsigned long long a0 = 0ull, a1 = 0ull;
            const ulonglong2* hp = (const ulonglong2*)hsm;
            #pragma unroll
            for (int q = 0; q < 16; ++q) {
                ulonglong2 hv = hp[q];
                fma2(a0, w0[2*q],   hv.x);
                fma2(a1, w0[2*q+1], hv.y);
            }
            const ulonglong2* fq = (const ulonglong2*)(featsm + ((t + 1) & 1)*16);
            #pragma unroll
            for (int q = 0; q < 4; ++q) {
                ulonglong2 fv = fq[q];
                fma2(a0, w0i[2*q],   fv.x);
                fma2(a1, w0i[2*q+1], fv.y);
            }
            float2 f0 = upk2(a0), f1 = upk2(a1);
            pg = bias0v + (f0.x + f0.y) + (f1.x + f1.y);   // gates0(t+1) pre-act
            acts[tid] = gact(tid, pg);
            __syncthreads();
        }
        if (tid == 0) relstore(&g_flag0[b], T_);
    } else if (blockIdx.x < 32) {
        // ============ mid: pre1 = wih1 @ h1 + bias (chunked GEMM, off critical path) ============
        const int b = blockIdx.x - 16;
        unsigned long long w1[32];
        {
            const float4* r1 = (const float4*)(wih1 + tid*64);
            #pragma unroll
            for (int q = 0; q < 16; ++q) {
                float4 a = r1[q]; w1[2*q] = pk2(a.x, a.y); w1[2*q+1] = pk2(a.z, a.w);
            }
        }
        const float bias1v = bih1[tid] + bhh1[tid];
        const float* h1B = g_h1 + (size_t)b * T_ * 64;
        float* pre1B = g_pre1 + (size_t)b * T_ * 256;
        int flagv = 0;

        for (int c = 0; c < T_/8; ++c) {
            int need = c*8 + 8;
            if (flagv < need) {
                do { flagv = acqload(&g_flag0[b]); if (flagv < need) __nanosleep(128); }
                while (flagv < need);
            }
            for (int i = tid; i < 512; i += 256) h1c[i] = h1B[c*512 + i];
            __syncthreads();
            #pragma unroll
            for (int j = 0; j < 8; ++j) {
                unsigned long long a0 = 0ull, a1 = 0ull;
                const ulonglong2* hp = (const ulonglong2*)(h1c + j*64);
                #pragma unroll
                for (int q = 0; q < 16; ++q) {
                    ulonglong2 hv = hp[q];
                    fma2(a0, w1[2*q],   hv.x);
                    fma2(a1, w1[2*q+1], hv.y);
                }
                float2 f0 = upk2(a0), f1 = upk2(a1);
                pre1B[(c*8 + j)*256 + tid] = bias1v + (f0.x + f0.y) + (f1.x + f1.y);
            }
            __syncthreads();
            if (tid == 0) relstore(&g_flag1[b], c*8 + 8);
        }
    } else {
        // ============ consumer: layer1 recurrence ============
        const int b = blockIdx.x - 32;
        unsigned long long w2r[32];
        {
            const float4* r2 = (const float4*)(whh1 + tid*64);
            #pragma unroll
            for (int q = 0; q < 16; ++q) {
                float4 a = r2[q]; w2r[2*q] = pk2(a.x, a.y); w2r[2*q+1] = pk2(a.z, a.w);
            }
        }
        const float* pre1B = g_pre1 + (size_t)b * T_ * 256;
        float* hB = g_h + (size_t)b * T_ * 64;
        float cst = 0.f;
        int flagv = 0;
        if (tid < 64) hsm[tid] = 0.f;
        while (flagv < 2) { flagv = acqload(&g_flag1[b]); if (flagv < 2) __nanosleep(1024); }
        float cg  = pre1B[tid];                  // gates1(0) pre-act (h2(-1)=0)
        float p1n = pre1B[256 + tid];            // pre1(1)
        acts[tid] = gact(tid, cg);
        __syncthreads();

        for (int t = 0; t < T_; ++t) {
            // phase 2: state update + h2 store
            if (tid < 64) {
                float c_ = acts[64 + tid]*cst + acts[tid]*acts[128 + tid];
                cst = c_;
                float h = acts[192 + tid]*tanhq(c_);
                hsm[tid] = h;
                hB[t*64 + tid] = h;
            }
            __syncthreads();
            // phase 3: whh1 dot with h2(t)
            unsigned long long a0 = 0ull, a1 = 0ull;
            const ulonglong2* hp = (const ulonglong2*)hsm;
            #pragma unroll
            for (int q = 0; q < 16; ++q) {
                ulonglong2 hv = hp[q];
                fma2(a0, w2r[2*q],   hv.x);
                fma2(a1, w2r[2*q+1], hv.y);
            }
            float2 f0 = upk2(a0), f1 = upk2(a1);
            cg = p1n + (f0.x + f0.y) + (f1.x + f1.y);   // gates1(t+1) pre-act
            acts[tid] = gact(tid, cg);
            int tn = (t + 2 < T_) ? t + 2 : T_ - 1;
            if (flagv < tn + 1) {
                do { flagv = acqload(&g_flag1[b]); if (flagv < tn + 1) __nanosleep(64); }
                while (flagv < tn + 1);
            }
            p1n = pre1B[tn*256 + tid];
            __syncthreads();
        }
    }
}

// ---------------- FC head ----------------
__global__ void __launch_bounds__(256) fc_kernel(
    const float* __restrict__ w1, const float* __restrict__ b1,
    const float* __restrict__ w2, const float* __restrict__ b2,
    float* __restrict__ out)
{
    __shared__ __align__(16) float w1s[2048];
    __shared__ float w2s[64];
    __shared__ float b1s[32];
    int tid = threadIdx.x;
    for (int i = tid; i < 2048; i += 256) w1s[i] = w1[i];
    if (tid < 64) w2s[tid] = w2[tid];
    if (tid < 32) b1s[tid] = b1[tid];
    __syncthreads();

    int gid = blockIdx.x*256 + tid;
    const float4* h4p = (const float4*)(g_h + (size_t)gid * 64);
    float4 h[16];
    #pragma unroll
    for (int q = 0; q < 16; ++q) h[q] = h4p[q];

    float l0 = b2[0], l1 = b2[1];
    #pragma unroll
    for (int i = 0; i < 32; ++i) {
        float acc = b1s[i];
        const float4* wr = (const float4*)(w1s + i*64);
        #pragma unroll
        for (int q = 0; q < 16; ++q) {
            float4 w4 = wr[q];
            acc += w4.x*h[q].x + w4.y*h[q].y + w4.z*h[q].z + w4.w*h[q].w;
        }
        acc = acc > 0.f ? acc : 0.f;
        l0 += w2s[i] * acc;
        l1 += w2s[32 + i] * acc;
    }
    ((float2*)out)[gid] = make_float2(l0, l1);
}

// ---------------- launch ----------------
extern "C" void kernel_launch(void* const* d_in, const int* in_sizes, int n_in,
                              void* d_out, int out_size)
{
    const float* x     = (const float*)d_in[0];
    const float* c1w   = (const float*)d_in[1];
    const float* c1b   = (const float*)d_in[2];
    const float* bn1g  = (const float*)d_in[3];
    const float* bn1b  = (const float*)d_in[4];
    const float* bn1m  = (const float*)d_in[5];
    const float* bn1v  = (const float*)d_in[6];
    const float* c2w   = (const float*)d_in[7];
    const float* c2b   = (const float*)d_in[8];
    const float* bn2g  = (const float*)d_in[9];
    const float* bn2b  = (const float*)d_in[10];
    const float* bn2m  = (const float*)d_in[11];
    const float* bn2v  = (const float*)d_in[12];
    const float* c3w   = (const float*)d_in[13];
    const float* c3b   = (const float*)d_in[14];
    const float* bn3g  = (const float*)d_in[15];
    const float* bn3b  = (const float*)d_in[16];
    const float* bn3m  = (const float*)d_in[17];
    const float* bn3v  = (const float*)d_in[18];
    const float* wih0  = (const float*)d_in[19];
    const float* whh0  = (const float*)d_in[20];
    const float* bih0  = (const float*)d_in[21];
    const float* bhh0  = (const float*)d_in[22];
    const float* wih1  = (const float*)d_in[23];
    const float* whh1  = (const float*)d_in[24];
    const float* bih1  = (const float*)d_in[25];
    const float* bhh1  = (const float*)d_in[26];
    const float* fc1w  = (const float*)d_in[27];
    const float* fc1b  = (const float*)d_in[28];
    const float* fc2w  = (const float*)d_in[29];
    const float* fc2b  = (const float*)d_in[30];

    cudaFuncSetAttribute(conv2g_kernel, cudaFuncAttributeMaxDynamicSharedMemorySize,
                         C2G_SMEM_FLOATS * 4);
    cudaFuncSetAttribute(bnd_lstm_kernel, cudaFuncAttributeMaxDynamicSharedMemorySize,
                         BND_SMEM_FLOATS * 4);

    // Phase A: global conv stack (conv1g also resets pipeline flags)
    conv1g_kernel<<<dim3(9, B_), 256>>>(x, c1w, c1b, bn1g, bn1b, bn1m, bn1v);
    conv2g_kernel<<<dim3(33, B_), 256, C2G_SMEM_FLOATS * 4>>>(c2w, c2b, bn2g, bn2b, bn2m, bn2v);
    conv3g_kernel<<<dim3(33, B_), 256>>>(c3w, c3b, bn3g, bn3b, bn3m, bn3v);

    // Fused Phase B + LSTM: lstm CTAs wave-1 resident, bnd CTAs fill the chip.
    bnd_lstm_kernel<<<48 + NBND, 256, BND_SMEM_FLOATS * 4>>>(
        x, c1w, c1b, bn1g, bn1b, bn1m, bn1v,
        c2w, bn2g, bn2v, c3w, bn3g, bn3v,
        wih0, whh0, bih0, bhh0, wih1, whh1, bih1, bhh1);

    // FC head
    fc_kernel<<<(B_ * T_) / 256, 256>>>(fc1w, fc1b, fc2w, fc2b, (float*)d_out);
}